// round 12
// baseline (speedup 1.0000x reference)
#include <cuda_runtime.h>
#include <math.h>

#define Kc 3
#define Bc 512
#define Dc 1024
#define Hc 512
#define Cc 48
#define Tc 25
#define G4 2048
#define DP1 1025
#define FEATN 6288
#define FEATNP 6304          // FEATN padded to mult of 16
#define XP 1040              // DP1 padded to mult of 16
#define LWP 1152             // lin_W col pad (9 n-blocks * 128)
#define D2 (2*Dc)

// output section offsets (all float32, concatenated in tuple order)
#define O0 0                                  // labels_t   [T,B]
#define O1 (Tc*Bc)                            // probs      [B,T,C]
#define O2 (O1 + Bc*Tc*Cc)                    // curr_action[B,C]
#define O3 (O2 + Bc*Cc)                       // durations  [B,T+1]
#define O4 (O3 + Bc*(Tc+1))                   // att_t      [T,B,D]

// ---------------- scratch (device globals: no allocation allowed) ----------
__device__ float d_Y[Kc*Bc*Cc];
__device__ float d_cls[Kc*Bc*Cc];     // classifier logits
__device__ float d_feat[Bc*FEATNP];
__device__ float d_x0p[Bc*XP];        // x0 padded [512][1040]
__device__ float d_xp[2*Bc*DP1];      // lin split-K partials
__device__ float d_gx0[Bc*G4];        // x0 @ W_ih^T + bsum
__device__ float d_E[Cc*G4];
__device__ float d_Ep[4*Cc*G4];
__device__ float d_P[Kc*Bc*Hc];
__device__ float d_sdur[Bc*Kc];
__device__ float d_gates[Bc*G4];
__device__ float d_h[2][Bc*Hc];
__device__ float d_c[Bc*Hc];
__device__ int   d_labels[Bc];
__device__ float d_dur[Bc];
__device__ float d_WpT[Cc*Hc];
__device__ float d_wihdur[G4];
__device__ float d_bsum[G4];
// presplit tf32 hi/lo weights
__device__ float d_Whh_hi[G4*Hc],     d_Whh_lo[G4*Hc];
__device__ float d_Wih_hi[G4*XP],     d_Wih_lo[G4*XP];
__device__ float d_linW_hi[FEATNP*LWP], d_linW_lo[FEATNP*LWP];
__device__ float d_Wat_hi[Hc*Dc],     d_Wat_lo[Hc*Dc];
__device__ float d_cWT_hi[Kc*Cc*D2],  d_cWT_lo[Kc*Cc*D2];

// ---------------- tf32 helpers ----------------------------------------------
__device__ __forceinline__ void tsplit(float x, float &hf, float &lf) {
    unsigned h, l;
    asm("cvt.rna.tf32.f32 %0, %1;" : "=r"(h) : "f"(x));
    hf = __uint_as_float(h);
    float r = x - hf;
    asm("cvt.rna.tf32.f32 %0, %1;" : "=r"(l) : "f"(r));
    lf = __uint_as_float(l);
}
__device__ __forceinline__ void ldm4(unsigned* r, unsigned addr) {
    asm volatile("ldmatrix.sync.aligned.m8n8.x4.shared.b16 {%0,%1,%2,%3}, [%4];"
        : "=r"(r[0]), "=r"(r[1]), "=r"(r[2]), "=r"(r[3]) : "r"(addr));
}
__device__ __forceinline__ void mma8(float* c, const unsigned* a, const unsigned* b) {
    asm volatile("mma.sync.aligned.m16n8k8.row.col.f32.tf32.tf32.f32 "
        "{%0,%1,%2,%3},{%4,%5,%6,%7},{%8,%9},{%0,%1,%2,%3};"
        : "+f"(c[0]), "+f"(c[1]), "+f"(c[2]), "+f"(c[3])
        : "r"(a[0]), "r"(a[1]), "r"(a[2]), "r"(a[3]), "r"(b[0]), "r"(b[1]));
}
// swizzled word index of 16B chunk start (row stride 20 f32, 4 data chunks)
__device__ __forceinline__ int swz(int row, int chunk) {
    return row*20 + (((chunk ^ (row >> 3)) & 3) << 2);
}

// ---------------- tgemm: 64x128 tile, 3xTF32, B presplit hi/lo --------------
// C[m,n] = sum_k A[m,k]*B'[k,n] (+bias[n]) (+C if ACC).  256 thr, KSTEP=16.
// BT=true : B is [N,K] row-major;  BT=false: B is [K,N] row-major.
// A split to tf32 hi/lo on the fly; B comes presplit (Bhi/Blo, same layout).
// K must be a multiple of 16.  z batches/split-K via sA/sB/sC strides.
template<bool BT, bool ACC>
__global__ void __launch_bounds__(256)
tgemm(const float* __restrict__ A,
      const float* __restrict__ Bhi, const float* __restrict__ Blo,
      float* __restrict__ C, int M, int N, int K,
      int lda, int ldb, int ldc, const float* __restrict__ bias,
      long long sA, long long sB, long long sC)
{
    __shared__ __align__(16) float As_hi[64*20], As_lo[64*20];
    __shared__ __align__(16) float Bs_hi[128*20], Bs_lo[128*20];

    A   += (size_t)blockIdx.z * sA;
    Bhi += (size_t)blockIdx.z * sB;
    Blo += (size_t)blockIdx.z * sB;
    C   += (size_t)blockIdx.z * sC;

    const int tid  = threadIdx.x;
    const int lane = tid & 31, wid = tid >> 5;
    const int m0 = blockIdx.y * 64, n0 = blockIdx.x * 128;
    const int am = (wid & 1) * 32;        // warp m-base (2 warps in m)
    const int an = (wid >> 1) * 32;       // warp n-base (4 warps in n)

    const unsigned aH = (unsigned)__cvta_generic_to_shared(As_hi);
    const unsigned aL = (unsigned)__cvta_generic_to_shared(As_lo);
    const unsigned bH = (unsigned)__cvta_generic_to_shared(Bs_hi);
    const unsigned bL = (unsigned)__cvta_generic_to_shared(Bs_lo);

    float acc[2][4][4];
#pragma unroll
    for (int i = 0; i < 2; i++)
#pragma unroll
        for (int j = 0; j < 4; j++)
#pragma unroll
            for (int q = 0; q < 4; q++) acc[i][j][q] = 0.f;

    for (int k0 = 0; k0 < K; k0 += 16) {
        // -------- global loads into regs --------
        float4 va = make_float4(0.f, 0.f, 0.f, 0.f);
        {
            int row = tid >> 2, kq = tid & 3;
            if (m0 + row < M)
                va = *(const float4*)&A[(size_t)(m0+row)*lda + k0 + 4*kq];
        }
        float4 vh0 = make_float4(0.f,0.f,0.f,0.f), vh1 = vh0, vl0 = vh0, vl1 = vh0;
        if (BT) {
            int n = tid >> 1, h8 = (tid & 1) * 8;
            if (n0 + n < N) {
                size_t off = (size_t)(n0+n)*ldb + k0 + h8;
                vh0 = *(const float4*)&Bhi[off];
                vh1 = *(const float4*)&Bhi[off + 4];
                vl0 = *(const float4*)&Blo[off];
                vl1 = *(const float4*)&Blo[off + 4];
            }
        } else {
            int k = tid >> 4, nq = tid & 15;
            size_t off = (size_t)(k0+k)*ldb + n0 + 8*nq;
            vh0 = *(const float4*)&Bhi[off];
            vh1 = *(const float4*)&Bhi[off + 4];
            vl0 = *(const float4*)&Blo[off];
            vl1 = *(const float4*)&Blo[off + 4];
        }
        __syncthreads();
        // -------- A split + stores, B direct stores --------
        {
            int row = tid >> 2, kq = tid & 3;
            float4 h4, l4;
            tsplit(va.x, h4.x, l4.x); tsplit(va.y, h4.y, l4.y);
            tsplit(va.z, h4.z, l4.z); tsplit(va.w, h4.w, l4.w);
            int w = swz(row, kq);
            *(float4*)&As_hi[w] = h4;
            *(float4*)&As_lo[w] = l4;
        }
        if (BT) {
            int n = tid >> 1, cb = (tid & 1) * 2;
            int w = swz(n, cb);
            *(float4*)&Bs_hi[w] = vh0; *(float4*)&Bs_lo[w] = vl0;
            w = swz(n, cb + 1);
            *(float4*)&Bs_hi[w] = vh1; *(float4*)&Bs_lo[w] = vl1;
        } else {
            int k = tid >> 4, nq = tid & 15;
            const float* ph0 = (const float*)&vh0;
            const float* ph1 = (const float*)&vh1;
            const float* pl0 = (const float*)&vl0;
            const float* pl1 = (const float*)&vl1;
#pragma unroll
            for (int e = 0; e < 4; e++) {
                int nl = 8*nq + e;
                int w = swz(nl, k >> 2) + (k & 3);
                Bs_hi[w] = ph0[e]; Bs_lo[w] = pl0[e];
                nl += 4; w = swz(nl, k >> 2) + (k & 3);
                Bs_hi[w] = ph1[e]; Bs_lo[w] = pl1[e];
            }
        }
        __syncthreads();
        // -------- compute: two k8 halves --------
#pragma unroll
        for (int half = 0; half < 2; half++) {
            const int kc = half * 8;
            unsigned ah[2][4], al[2][4], bh[4][2], bl[4][2];
#pragma unroll
            for (int i = 0; i < 2; i++) {
                int row = am + 16*i + (lane & 15);
                int chunk = (kc >> 2) + (lane >> 4);
                unsigned off = 4u * (unsigned)swz(row, chunk);
                ldm4(ah[i], aH + off);
                ldm4(al[i], aL + off);
            }
#pragma unroll
            for (int g = 0; g < 2; g++) {
                int row = an + 16*g + (lane & 7) + ((lane >> 4) << 3);
                int chunk = (kc >> 2) + ((lane >> 3) & 1);
                unsigned off = 4u * (unsigned)swz(row, chunk);
                unsigned r[4];
                ldm4(r, bH + off);
                bh[2*g][0] = r[0]; bh[2*g][1] = r[1];
                bh[2*g+1][0] = r[2]; bh[2*g+1][1] = r[3];
                ldm4(r, bL + off);
                bl[2*g][0] = r[0]; bl[2*g][1] = r[1];
                bl[2*g+1][0] = r[2]; bl[2*g+1][1] = r[3];
            }
#pragma unroll
            for (int i = 0; i < 2; i++)
#pragma unroll
                for (int j = 0; j < 4; j++) {
                    mma8(acc[i][j], ah[i], bh[j]);
                    mma8(acc[i][j], ah[i], bl[j]);
                    mma8(acc[i][j], al[i], bh[j]);
                }
        }
    }

    // -------- epilogue --------
#pragma unroll
    for (int i = 0; i < 2; i++) {
#pragma unroll
        for (int j = 0; j < 4; j++) {
            int r0 = m0 + am + 16*i + (lane >> 2);
            int c0 = n0 + an + 8*j + (lane & 3) * 2;
            float b0 = 0.f, b1 = 0.f;
            if (bias) {
                if (c0 < N)     b0 = bias[c0];
                if (c0 + 1 < N) b1 = bias[c0 + 1];
            }
            if (r0 < M) {
                float* p = &C[(size_t)r0*ldc + c0];
                if (c0 < N)     p[0] = acc[i][j][0] + b0 + (ACC ? p[0] : 0.f);
                if (c0 + 1 < N) p[1] = acc[i][j][1] + b1 + (ACC ? p[1] : 0.f);
            }
            if (r0 + 8 < M) {
                float* p = &C[(size_t)(r0+8)*ldc + c0];
                if (c0 < N)     p[0] = acc[i][j][2] + b0 + (ACC ? p[0] : 0.f);
                if (c0 + 1 < N) p[1] = acc[i][j][3] + b1 + (ACC ? p[1] : 0.f);
            }
        }
    }
}

// ---------------- pad + tf32-split copy -------------------------------------
__global__ void pad_split(const float* __restrict__ src,
                          float* __restrict__ dhi, float* __restrict__ dlo,
                          int srows, int scols, int drows, int dcols)
{
    for (long long i = blockIdx.x*(long long)blockDim.x + threadIdx.x;
         i < (long long)drows*dcols; i += (long long)gridDim.x*blockDim.x) {
        int r = (int)(i / dcols), c = (int)(i % dcols);
        float v = (r < srows && c < scols) ? src[(size_t)r*scols + c] : 0.f;
        float h, l; tsplit(v, h, l);
        dhi[i] = h; dlo[i] = l;
    }
}

// transpose cls_W [k][2D][C] -> [k][C][2D] with tf32 split
__global__ void cls_tsplit(const float* __restrict__ W)
{
    for (int i = blockIdx.x*blockDim.x + threadIdx.x; i < Kc*D2*Cc;
         i += gridDim.x*blockDim.x) {
        int k = i / (D2*Cc), rem = i % (D2*Cc);
        int d = rem / Cc, c = rem % Cc;
        float h, l; tsplit(W[i], h, l);
        size_t o = (size_t)k*Cc*D2 + (size_t)c*D2 + d;
        d_cWT_hi[o] = h; d_cWT_lo[o] = l;
    }
}

// ---------------- split-K reduce (E) + padded reduce (x0) -------------------
__global__ void reduce_add(const float* __restrict__ part, float* __restrict__ outp,
                           int n, int nparts, long long stride)
{
    int i = blockIdx.x * blockDim.x + threadIdx.x;
    if (i >= n) return;
    float s = 0.f;
    for (int z = 0; z < nparts; z++) s += part[(size_t)z*stride + i];
    outp[i] = s;
}

__global__ void reduce_x0(const float* __restrict__ lin_b)
{
    int i = blockIdx.x * blockDim.x + threadIdx.x;
    if (i >= Bc*XP) return;
    int row = i / XP, col = i % XP;
    float v = 0.f;
    if (col < DP1)
        v = d_xp[(size_t)row*DP1 + col] + d_xp[(size_t)Bc*DP1 + (size_t)row*DP1 + col]
          + lin_b[col];
    d_x0p[i] = v;
}

// ---------------- init ------------------------------------------------------
__global__ void init_kernel(const float* __restrict__ W_ih,
                            const float* __restrict__ b_ih,
                            const float* __restrict__ b_hh,
                            const float* __restrict__ Wp)
{
    for (int i = blockIdx.x*blockDim.x + threadIdx.x; i < Bc*Hc;
         i += gridDim.x*blockDim.x) {
        d_h[0][i] = 0.f; d_c[i] = 0.f;
        if (i < Cc*Hc) {
            int c = i >> 9, h = i & 511;
            d_WpT[i] = Wp[h*Cc + c];
        }
        if (i < G4) {
            d_wihdur[i] = W_ih[(size_t)i*DP1 + Dc];
            d_bsum[i]   = b_ih[i] + b_hh[i];
        }
    }
}

// ---------------- classifier softmax: logits -> probs -----------------------
__global__ void cls_softmax(const float* __restrict__ bcls)
{
    const int kb = blockIdx.x;            // k*Bc + b
    const int k = kb >> 9;
    const float* row = d_cls + (size_t)kb * Cc;
    float* yr = d_Y + (size_t)kb * Cc;
    int lane = threadIdx.x;
    float v1 = row[lane] + bcls[k*Cc + lane];
    float v2 = (lane + 32 < Cc) ? row[lane + 32] + bcls[k*Cc + lane + 32] : -3.4e38f;
    float m = fmaxf(v1, v2);
    for (int o = 16; o; o >>= 1) m = fmaxf(m, __shfl_xor_sync(0xffffffffu, m, o));
    float e1 = expf(v1 - m);
    float e2 = (lane + 32 < Cc) ? expf(v2 - m) : 0.f;
    float s = e1 + e2;
    for (int o = 16; o; o >>= 1) s += __shfl_xor_sync(0xffffffffu, s, o);
    float inv = 1.f / s;
    yr[lane] = e1 * inv;
    if (lane + 32 < Cc) yr[lane + 32] = e2 * inv;
}

// feat assembly + curr_action + curr_dur + sdur ; one block per b
__global__ void prep_kernel(const float* __restrict__ S, const float* __restrict__ R,
                            const float* __restrict__ dur_W, const float* __restrict__ dur_b,
                            const float* __restrict__ Wdur, float* __restrict__ out)
{
    __shared__ float red[256];
    const int b = blockIdx.x, tid = threadIdx.x;
    float* fr = d_feat + (size_t)b * FEATNP;
    for (int i = tid; i < Kc*Cc; i += 256) {
        int k = i / Cc, c = i - k*Cc;
        fr[i] = d_Y[((size_t)k*Bc + b)*Cc + c];
    }
    for (int i = tid; i < Kc*Dc; i += 256) {
        int k = i >> 10, d = i & 1023;
        fr[Kc*Cc + i]         = S[((size_t)k*Bc + b)*Dc + d];
        fr[Kc*Cc + Kc*Dc + i] = R[((size_t)k*Bc + b)*Dc + d];
    }
    if (tid < FEATNP - FEATN) fr[FEATN + tid] = 0.f;   // zero pad cols
    for (int i = tid; i < Cc; i += 256)
        out[O2 + (size_t)b*Cc + i] = d_Y[(size_t)b*Cc + i]
                                   + d_Y[((size_t)Bc + b)*Cc + i]
                                   + d_Y[((size_t)2*Bc + b)*Cc + i];
    float pd = 0.f;
    for (int i = tid; i < Kc*Dc; i += 256) {
        int k = i >> 10, d = i & 1023;
        pd += R[((size_t)k*Bc + b)*Dc + d] * dur_W[i];
    }
    red[tid] = pd; __syncthreads();
    for (int s = 128; s > 0; s >>= 1) { if (tid < s) red[tid] += red[tid + s]; __syncthreads(); }
    if (tid == 0) out[O3 + (size_t)b*(Tc+1)] = red[0] + dur_b[0];
    __syncthreads();
    for (int k = 0; k < Kc; k++) {
        float ps = 0.f;
        for (int d = tid; d < Dc; d += 256)
            ps += S[((size_t)k*Bc + b)*Dc + d] * Wdur[d];
        red[tid] = ps; __syncthreads();
        for (int s = 128; s > 0; s >>= 1) { if (tid < s) red[tid] += red[tid + s]; __syncthreads(); }
        if (tid == 0) d_sdur[b*Kc + k] = red[0];
        __syncthreads();
    }
}

// fused per-step kernel: LSTM elementwise + logits/probs/argmax + attention +
// dur ; one block per b, 512 threads (16 warps). bsum already folded in GEMMs.
__global__ void __launch_bounds__(512)
step_kernel(const float* __restrict__ S, const float* __restrict__ bp,
            const float* __restrict__ Wdur, const float* __restrict__ bdur,
            float* __restrict__ out, int t, int sel)
{
    __shared__ float sh[Hc];
    __shared__ float slog[Cc];
    __shared__ float sscore[3];
    __shared__ float saw[3];
    __shared__ float sred[16];
    const int b  = blockIdx.x;
    const int th = threadIdx.x;
    const int wid = th >> 5, lane = th & 31;
    const float* h_in = d_h[sel];
    float* h_out = d_h[sel ^ 1];

    float g[4];
    if (t == 0) {
#pragma unroll
        for (int j = 0; j < 4; j++) g[j] = d_gx0[(size_t)b*G4 + j*Hc + th];
    } else {
        int lab = d_labels[b];
        float dp = d_dur[b];
#pragma unroll
        for (int j = 0; j < 4; j++) {
            int gi = j*Hc + th;
            g[j] = d_gates[(size_t)b*G4 + gi] + d_E[(size_t)lab*G4 + gi]
                 + dp * d_wihdur[gi];
        }
    }
    float ig = 1.f / (1.f + expf(-g[0]));
    float fg = 1.f / (1.f + expf(-g[1]));
    float gg = tanhf(g[2]);
    float og = 1.f / (1.f + expf(-g[3]));
    int idx = b*Hc + th;
    float cn = fg * d_c[idx] + ig * gg;
    d_c[idx] = cn;
    float hn = og * tanhf(cn);
    h_out[idx] = hn;
    sh[th] = hn;
    float hp = h_in[idx] * Wdur[Dc + th];
    for (int o = 16; o; o >>= 1) hp += __shfl_xor_sync(0xffffffffu, hp, o);
    if (lane == 0) sred[wid] = hp;
    __syncthreads();

    for (int cc = wid; cc < Cc; cc += 16) {
        float s = 0.f;
        const float* wr = d_WpT + (size_t)cc*Hc;
        for (int j = lane; j < Hc; j += 32) s += sh[j] * wr[j];
        for (int o = 16; o; o >>= 1) s += __shfl_xor_sync(0xffffffffu, s, o);
        if (lane == 0) slog[cc] = s + bp[cc];
    }
    if (wid < 3) {
        float s = 0.f;
        const float* Pr = d_P + ((size_t)wid*Bc + b)*Hc;
        for (int j = lane; j < Hc; j += 32) s += sh[j] * Pr[j];
        for (int o = 16; o; o >>= 1) s += __shfl_xor_sync(0xffffffffu, s, o);
        if (lane == 0) sscore[wid] = s * 0.03125f;  // 1/sqrt(1024)
    }
    __syncthreads();

    if (wid == 0) {
        float v1 = slog[lane];
        float v2 = (lane < Cc - 32) ? slog[32 + lane] : -3.4e38f;
        float m = fmaxf(v1, v2);
        for (int o = 16; o; o >>= 1) m = fmaxf(m, __shfl_xor_sync(0xffffffffu, m, o));
        float e1 = expf(v1 - m);
        float e2 = (lane < Cc - 32) ? expf(v2 - m) : 0.f;
        float s = e1 + e2;
        for (int o = 16; o; o >>= 1) s += __shfl_xor_sync(0xffffffffu, s, o);
        float inv = 1.f / s;
        size_t pb = O1 + ((size_t)b*Tc + t)*Cc;
        out[pb + lane] = e1 * inv;
        if (lane < Cc - 32) out[pb + 32 + lane] = e2 * inv;
        float bv; int bi;
        if (lane < Cc - 32 && v2 > v1) { bv = v2; bi = 32 + lane; }
        else                           { bv = v1; bi = lane; }
        for (int o = 16; o; o >>= 1) {
            float ov = __shfl_xor_sync(0xffffffffu, bv, o);
            int   oi = __shfl_xor_sync(0xffffffffu, bi, o);
            if (ov > bv || (ov == bv && oi < bi)) { bv = ov; bi = oi; }
        }
        float hv = (lane < 16) ? sred[lane] : 0.f;
        for (int o = 8; o; o >>= 1) hv += __shfl_xor_sync(0xffffffffu, hv, o);
        if (lane == 0) {
            out[O0 + (size_t)t*Bc + b] = (float)bi;
            d_labels[b] = bi;
            float s0 = sscore[0], s1 = sscore[1], s2 = sscore[2];
            float sm = fmaxf(s0, fmaxf(s1, s2));
            float a0 = expf(s0 - sm), a1 = expf(s1 - sm), a2 = expf(s2 - sm);
            float z = 1.f / (a0 + a1 + a2);
            a0 *= z; a1 *= z; a2 *= z;
            saw[0] = a0; saw[1] = a1; saw[2] = a2;
            float dur = a0*d_sdur[b*Kc] + a1*d_sdur[b*Kc+1] + a2*d_sdur[b*Kc+2]
                      + hv + bdur[0];
            out[O3 + (size_t)b*(Tc+1) + t + 1] = dur;
            d_dur[b] = dur;
        }
    }
    __syncthreads();

    float a0 = saw[0], a1 = saw[1], a2 = saw[2];
    size_t ab = O4 + ((size_t)t*Bc + b)*Dc;
    const float* S0 = S + (size_t)b*Dc;
    const float* S1 = S + ((size_t)Bc + b)*Dc;
    const float* S2 = S + ((size_t)2*Bc + b)*Dc;
    for (int d = th; d < Dc; d += 512)
        out[ab + d] = a0*S0[d] + a1*S1[d] + a2*S2[d];
}

// ---------------- host ------------------------------------------------------
extern "C" void kernel_launch(void* const* d_in, const int* in_sizes, int n_in,
                              void* d_out, int out_size)
{
    const float* S     = (const float*)d_in[0];
    const float* R     = (const float*)d_in[1];
    const float* cls_W = (const float*)d_in[2];
    const float* cls_b = (const float*)d_in[3];
    const float* dur_W = (const float*)d_in[4];
    const float* dur_b = (const float*)d_in[5];
    const float* lin_W = (const float*)d_in[6];
    const float* lin_b = (const float*)d_in[7];
    const float* W_ih  = (const float*)d_in[8];
    const float* W_hh  = (const float*)d_in[9];
    const float* b_ih  = (const float*)d_in[10];
    const float* b_hh  = (const float*)d_in[11];
    const float* Wp    = (const float*)d_in[12];
    const float* bp    = (const float*)d_in[13];
    const float* Wdur  = (const float*)d_in[14];
    const float* bdur  = (const float*)d_in[15];
    const float* embed = (const float*)d_in[16];
    const float* Wattn = (const float*)d_in[17];
    float* out = (float*)d_out;

    float *pfeat, *px0p, *pgx0, *pE, *pEp, *pP, *pgates, *ph, *pbsum, *pxp, *pcls;
    float *pWhh_hi, *pWhh_lo, *pWih_hi, *pWih_lo, *plinW_hi, *plinW_lo;
    float *pWat_hi, *pWat_lo, *pcWT_hi, *pcWT_lo;
    cudaGetSymbolAddress((void**)&pfeat,   d_feat);
    cudaGetSymbolAddress((void**)&px0p,    d_x0p);
    cudaGetSymbolAddress((void**)&pxp,     d_xp);
    cudaGetSymbolAddress((void**)&pgx0,    d_gx0);
    cudaGetSymbolAddress((void**)&pE,      d_E);
    cudaGetSymbolAddress((void**)&pEp,     d_Ep);
    cudaGetSymbolAddress((void**)&pP,      d_P);
    cudaGetSymbolAddress((void**)&pgates,  d_gates);
    cudaGetSymbolAddress((void**)&ph,      d_h);
    cudaGetSymbolAddress((void**)&pbsum,   d_bsum);
    cudaGetSymbolAddress((void**)&pcls,    d_cls);
    cudaGetSymbolAddress((void**)&pWhh_hi, d_Whh_hi);
    cudaGetSymbolAddress((void**)&pWhh_lo, d_Whh_lo);
    cudaGetSymbolAddress((void**)&pWih_hi, d_Wih_hi);
    cudaGetSymbolAddress((void**)&pWih_lo, d_Wih_lo);
    cudaGetSymbolAddress((void**)&plinW_hi, d_linW_hi);
    cudaGetSymbolAddress((void**)&plinW_lo, d_linW_lo);
    cudaGetSymbolAddress((void**)&pWat_hi, d_Wat_hi);
    cudaGetSymbolAddress((void**)&pWat_lo, d_Wat_lo);
    cudaGetSymbolAddress((void**)&pcWT_hi, d_cWT_hi);
    cudaGetSymbolAddress((void**)&pcWT_lo, d_cWT_lo);

    init_kernel<<<256, 512>>>(W_ih, b_ih, b_hh, Wp);
    // presplit static weights into tf32 hi/lo (padded where needed)
    pad_split<<<512, 256>>>(W_hh,  pWhh_hi,  pWhh_lo,  G4, Hc,  G4, Hc);
    pad_split<<<512, 256>>>(W_ih,  pWih_hi,  pWih_lo,  G4, DP1, G4, XP);
    pad_split<<<1024, 256>>>(lin_W, plinW_hi, plinW_lo, FEATN, DP1, FEATNP, LWP);
    pad_split<<<512, 256>>>(Wattn, pWat_hi,  pWat_lo,  Hc, Dc,  Hc, Dc);
    cls_tsplit<<<512, 256>>>(cls_W);

    // classifier logits via tensor GEMM: S-part then R-part (accumulate)
    tgemm<true, false><<<dim3(1, 8, 3), 256>>>(
        S, pcWT_hi, pcWT_lo, pcls, Bc, Cc, Dc, Dc, D2, Cc, nullptr,
        (long long)Bc*Dc, (long long)Cc*D2, (long long)Bc*Cc);
    tgemm<true, true><<<dim3(1, 8, 3), 256>>>(
        R, pcWT_hi + Dc, pcWT_lo + Dc, pcls, Bc, Cc, Dc, Dc, D2, Cc, nullptr,
        (long long)Bc*Dc, (long long)Cc*D2, (long long)Bc*Cc);
    cls_softmax<<<Kc*Bc, 32>>>(cls_b);
    prep_kernel<<<Bc, 256>>>(S, R, dur_W, dur_b, Wdur, out);

    // x0 = feat @ lin_W + lin_b  [512 x 1025, K=6304]  split-K 2 (144 blocks)
    tgemm<false, false><<<dim3(9, 8, 2), 256>>>(
        pfeat, plinW_hi, plinW_lo, pxp, Bc, DP1, FEATNP/2, FEATNP, LWP, DP1, nullptr,
        (long long)(FEATNP/2), (long long)(FEATNP/2)*LWP, (long long)Bc*DP1);
    reduce_x0<<<(Bc*XP + 255)/256, 256>>>(lin_b);
    // gx0 = x0 @ W_ih^T + bsum  [512 x 2048, K=1040]  (128 blocks)
    tgemm<true, false><<<dim3(16, 8), 256>>>(
        px0p, pWih_hi, pWih_lo, pgx0, Bc, G4, XP, XP, XP, G4, pbsum, 0, 0, 0);
    // E = embed @ W_ih[:, :D]^T  [48 x 2048, K=1024]  split-K 4 (64 blocks)
    tgemm<true, false><<<dim3(16, 1, 4), 256>>>(
        embed, pWih_hi, pWih_lo, pEp, Cc, G4, Dc/4, Dc, XP, G4, nullptr,
        (long long)(Dc/4), (long long)(Dc/4), (long long)Cc*G4);
    reduce_add<<<(Cc*G4 + 255)/256, 256>>>(pEp, pE, Cc*G4, 4, (long long)Cc*G4);
    // P = S_flat @ Wattn^T  [1536 x 512, K=1024]  (96 blocks)
    tgemm<true, false><<<dim3(4, 24), 256>>>(
        S, pWat_hi, pWat_lo, pP, Kc*Bc, Hc, Dc, Dc, Dc, Hc, nullptr, 0, 0, 0);

    int sel = 0;
    for (int t = 0; t < Tc; t++) {
        if (t > 0)
            tgemm<true, false><<<dim3(16, 8), 256>>>(
                ph + (size_t)sel*Bc*Hc, pWhh_hi, pWhh_lo, pgates,
                Bc, G4, Hc, Hc, Hc, G4, pbsum, 0, 0, 0);
        step_kernel<<<Bc, 512>>>(S, bp, Wdur, bdur, out, t, sel);
        sel ^= 1;
    }
}

// round 13
// speedup vs baseline: 1.1479x; 1.1479x over previous
#include <cuda_runtime.h>
#include <math.h>

#define Kc 3
#define Bc 512
#define Dc 1024
#define Hc 512
#define Cc 48
#define Tc 25
#define G4 2048
#define DP1 1025
#define FEATN 6288
#define FEATNP 6304          // FEATN padded to mult of 16
#define XP 1040              // DP1 padded to mult of 16
#define LWP 1152             // lin_W col pad (9 n-blocks * 128)
#define D2 (2*Dc)

// output section offsets (all float32, concatenated in tuple order)
#define O0 0                                  // labels_t   [T,B]
#define O1 (Tc*Bc)                            // probs      [B,T,C]
#define O2 (O1 + Bc*Tc*Cc)                    // curr_action[B,C]
#define O3 (O2 + Bc*Cc)                       // durations  [B,T+1]
#define O4 (O3 + Bc*(Tc+1))                   // att_t      [T,B,D]

// ---------------- scratch (device globals: no allocation allowed) ----------
__device__ float d_Y[Kc*Bc*Cc];
__device__ float d_cls[Kc*Bc*Cc];     // classifier logits
__device__ float d_cWT[Kc*Cc*D2];     // cls_W transposed [k][C][2D]
__device__ float d_feat[Bc*FEATNP];
__device__ float d_x0p[Bc*XP];        // x0 padded [512][1040]
__device__ float d_xp[2*Bc*DP1];      // lin split-K partials
__device__ float d_gx0[Bc*G4];        // x0 @ W_ih^T + bsum
__device__ float d_E[Cc*G4];
__device__ float d_Ep[4*Cc*G4];
__device__ float d_P[Kc*Bc*Hc];
__device__ float d_sdur[Bc*Kc];
__device__ float d_gates[Bc*G4];
__device__ float d_h[2][Bc*Hc];
__device__ float d_c[Bc*Hc];
__device__ int   d_labels[Bc];
__device__ float d_dur[Bc];
__device__ float d_WpT[Cc*Hc];
__device__ float d_wihdur[G4];
__device__ float d_bsum[G4];
__device__ float d_Wihp[G4*XP];       // W_ih padded [2048][1040]
__device__ float d_linWp[FEATNP*LWP]; // lin_W padded [6304][1152]

// ---------------- tf32 helpers ----------------------------------------------
__device__ __forceinline__ void tsplit(float x, float &hf, float &lf) {
    unsigned h, l;
    asm("cvt.rna.tf32.f32 %0, %1;" : "=r"(h) : "f"(x));
    hf = __uint_as_float(h);
    float r = x - hf;
    asm("cvt.rna.tf32.f32 %0, %1;" : "=r"(l) : "f"(r));
    lf = __uint_as_float(l);
}
__device__ __forceinline__ void ldm4(unsigned* r, unsigned addr) {
    asm volatile("ldmatrix.sync.aligned.m8n8.x4.shared.b16 {%0,%1,%2,%3}, [%4];"
        : "=r"(r[0]), "=r"(r[1]), "=r"(r[2]), "=r"(r[3]) : "r"(addr));
}
__device__ __forceinline__ void mma8(float* c, const unsigned* a, const unsigned* b) {
    asm volatile("mma.sync.aligned.m16n8k8.row.col.f32.tf32.tf32.f32 "
        "{%0,%1,%2,%3},{%4,%5,%6,%7},{%8,%9},{%0,%1,%2,%3};"
        : "+f"(c[0]), "+f"(c[1]), "+f"(c[2]), "+f"(c[3])
        : "r"(a[0]), "r"(a[1]), "r"(a[2]), "r"(a[3]), "r"(b[0]), "r"(b[1]));
}
// swizzled word index of 16B chunk start (row stride 20 f32, 4 data chunks)
__device__ __forceinline__ int swz(int row, int chunk) {
    return row*20 + (((chunk ^ (row >> 3)) & 3) << 2);
}

// ---------------- tgemm: 64x128 tile, 3xTF32, NT/NN -------------------------
// C[m,n] = sum_k A[m,k]*B'[k,n] (+bias[n]) (+C if ACC).  256 thr, KSTEP=16.
// BT=true : B is [N,K] row-major;  BT=false: B is [K,N] row-major.
// K must be a multiple of 16 (pad arrays with zeros).  z batches/split-K.
template<bool BT, bool ACC>
__global__ void __launch_bounds__(256)
tgemm(const float* __restrict__ A, const float* __restrict__ Bm,
      float* __restrict__ C, int M, int N, int K,
      int lda, int ldb, int ldc, const float* __restrict__ bias,
      long long sA, long long sB, long long sC)
{
    __shared__ __align__(16) float As_hi[64*20], As_lo[64*20];
    __shared__ __align__(16) float Bs_hi[128*20], Bs_lo[128*20];

    A  += (size_t)blockIdx.z * sA;
    Bm += (size_t)blockIdx.z * sB;
    C  += (size_t)blockIdx.z * sC;

    const int tid  = threadIdx.x;
    const int lane = tid & 31, wid = tid >> 5;
    const int m0 = blockIdx.y * 64, n0 = blockIdx.x * 128;
    const int am = (wid & 1) * 32;        // warp m-base (2 warps in m)
    const int an = (wid >> 1) * 32;       // warp n-base (4 warps in n)

    const unsigned aH = (unsigned)__cvta_generic_to_shared(As_hi);
    const unsigned aL = (unsigned)__cvta_generic_to_shared(As_lo);
    const unsigned bH = (unsigned)__cvta_generic_to_shared(Bs_hi);
    const unsigned bL = (unsigned)__cvta_generic_to_shared(Bs_lo);

    float acc[2][4][4];
#pragma unroll
    for (int i = 0; i < 2; i++)
#pragma unroll
        for (int j = 0; j < 4; j++)
#pragma unroll
            for (int q = 0; q < 4; q++) acc[i][j][q] = 0.f;

    for (int k0 = 0; k0 < K; k0 += 16) {
        // -------- global loads into regs --------
        float4 va = make_float4(0.f, 0.f, 0.f, 0.f);
        {
            int row = tid >> 2, kq = tid & 3;
            if (m0 + row < M)
                va = *(const float4*)&A[(size_t)(m0+row)*lda + k0 + 4*kq];
        }
        float4 vb0 = make_float4(0.f,0.f,0.f,0.f), vb1 = vb0;
        if (BT) {
            int n = tid >> 1, h8 = (tid & 1) * 8;
            if (n0 + n < N) {
                const float* src = &Bm[(size_t)(n0+n)*ldb + k0 + h8];
                vb0 = *(const float4*)src;
                vb1 = *(const float4*)(src + 4);
            }
        } else {
            int k = tid >> 4, nq = tid & 15;
            const float* src = &Bm[(size_t)(k0+k)*ldb + n0 + 8*nq];
            vb0 = *(const float4*)src;
            vb1 = *(const float4*)(src + 4);
        }
        __syncthreads();
        // -------- split + smem stores --------
        {
            int row = tid >> 2, kq = tid & 3;
            float4 h4, l4;
            tsplit(va.x, h4.x, l4.x); tsplit(va.y, h4.y, l4.y);
            tsplit(va.z, h4.z, l4.z); tsplit(va.w, h4.w, l4.w);
            int w = swz(row, kq);
            *(float4*)&As_hi[w] = h4;
            *(float4*)&As_lo[w] = l4;
        }
        if (BT) {
            int n = tid >> 1, cb = (tid & 1) * 2;
            float4 h4, l4;
            tsplit(vb0.x, h4.x, l4.x); tsplit(vb0.y, h4.y, l4.y);
            tsplit(vb0.z, h4.z, l4.z); tsplit(vb0.w, h4.w, l4.w);
            int w = swz(n, cb);
            *(float4*)&Bs_hi[w] = h4; *(float4*)&Bs_lo[w] = l4;
            tsplit(vb1.x, h4.x, l4.x); tsplit(vb1.y, h4.y, l4.y);
            tsplit(vb1.z, h4.z, l4.z); tsplit(vb1.w, h4.w, l4.w);
            w = swz(n, cb + 1);
            *(float4*)&Bs_hi[w] = h4; *(float4*)&Bs_lo[w] = l4;
        } else {
            int k = tid >> 4, nq = tid & 15;
            const float* p0 = (const float*)&vb0;
            const float* p1 = (const float*)&vb1;
#pragma unroll
            for (int e = 0; e < 4; e++) {
                float hv, lv;
                int nl = 8*nq + e;
                int w = swz(nl, k >> 2) + (k & 3);
                tsplit(p0[e], hv, lv); Bs_hi[w] = hv; Bs_lo[w] = lv;
                nl += 4; w = swz(nl, k >> 2) + (k & 3);
                tsplit(p1[e], hv, lv); Bs_hi[w] = hv; Bs_lo[w] = lv;
            }
        }
        __syncthreads();
        // -------- compute: two k8 halves --------
#pragma unroll
        for (int half = 0; half < 2; half++) {
            const int kc = half * 8;
            unsigned ah[2][4], al[2][4], bh[4][2], bl[4][2];
#pragma unroll
            for (int i = 0; i < 2; i++) {
                int row = am + 16*i + (lane & 15);
                int chunk = (kc >> 2) + (lane >> 4);
                unsigned off = 4u * (unsigned)swz(row, chunk);
                ldm4(ah[i], aH + off);
                ldm4(al[i], aL + off);
            }
#pragma unroll
            for (int g = 0; g < 2; g++) {
                int row = an + 16*g + (lane & 7) + ((lane >> 4) << 3);
                int chunk = (kc >> 2) + ((lane >> 3) & 1);
                unsigned off = 4u * (unsigned)swz(row, chunk);
                unsigned r[4];
                ldm4(r, bH + off);
                bh[2*g][0] = r[0]; bh[2*g][1] = r[1];
                bh[2*g+1][0] = r[2]; bh[2*g+1][1] = r[3];
                ldm4(r, bL + off);
                bl[2*g][0] = r[0]; bl[2*g][1] = r[1];
                bl[2*g+1][0] = r[2]; bl[2*g+1][1] = r[3];
            }
#pragma unroll
            for (int i = 0; i < 2; i++)
#pragma unroll
                for (int j = 0; j < 4; j++) {
                    mma8(acc[i][j], ah[i], bh[j]);
                    mma8(acc[i][j], ah[i], bl[j]);
                    mma8(acc[i][j], al[i], bh[j]);
                }
        }
    }

    // -------- epilogue --------
#pragma unroll
    for (int i = 0; i < 2; i++) {
#pragma unroll
        for (int j = 0; j < 4; j++) {
            int r0 = m0 + am + 16*i + (lane >> 2);
            int c0 = n0 + an + 8*j + (lane & 3) * 2;
            float b0 = 0.f, b1 = 0.f;
            if (bias) {
                if (c0 < N)     b0 = bias[c0];
                if (c0 + 1 < N) b1 = bias[c0 + 1];
            }
            if (r0 < M) {
                float* p = &C[(size_t)r0*ldc + c0];
                if (c0 < N)     p[0] = acc[i][j][0] + b0 + (ACC ? p[0] : 0.f);
                if (c0 + 1 < N) p[1] = acc[i][j][1] + b1 + (ACC ? p[1] : 0.f);
            }
            if (r0 + 8 < M) {
                float* p = &C[(size_t)(r0+8)*ldc + c0];
                if (c0 < N)     p[0] = acc[i][j][2] + b0 + (ACC ? p[0] : 0.f);
                if (c0 + 1 < N) p[1] = acc[i][j][3] + b1 + (ACC ? p[1] : 0.f);
            }
        }
    }
}

// ---------------- pad copy ---------------------------------------------------
__global__ void pad_copy(const float* __restrict__ src, float* __restrict__ dst,
                         int srows, int scols, int drows, int dcols)
{
    for (long long i = blockIdx.x*(long long)blockDim.x + threadIdx.x;
         i < (long long)drows*dcols; i += (long long)gridDim.x*blockDim.x) {
        int r = (int)(i / dcols), c = (int)(i % dcols);
        dst[i] = (r < srows && c < scols) ? src[(size_t)r*scols + c] : 0.f;
    }
}

// transpose cls_W [k][2D][C] -> [k][C][2D]
__global__ void cls_T(const float* __restrict__ W)
{
    for (int i = blockIdx.x*blockDim.x + threadIdx.x; i < Kc*D2*Cc;
         i += gridDim.x*blockDim.x) {
        int k = i / (D2*Cc), rem = i % (D2*Cc);
        int d = rem / Cc, c = rem % Cc;
        d_cWT[(size_t)k*Cc*D2 + (size_t)c*D2 + d] = W[i];
    }
}

// ---------------- split-K reduce (E) + padded reduce (x0) -------------------
__global__ void reduce_add(const float* __restrict__ part, float* __restrict__ outp,
                           int n, int nparts, long long stride)
{
    int i = blockIdx.x * blockDim.x + threadIdx.x;
    if (i >= n) return;
    float s = 0.f;
    for (int z = 0; z < nparts; z++) s += part[(size_t)z*stride + i];
    outp[i] = s;
}

__global__ void reduce_x0(const float* __restrict__ lin_b)
{
    int i = blockIdx.x * blockDim.x + threadIdx.x;
    if (i >= Bc*XP) return;
    int row = i / XP, col = i % XP;
    float v = 0.f;
    if (col < DP1)
        v = d_xp[(size_t)row*DP1 + col] + d_xp[(size_t)Bc*DP1 + (size_t)row*DP1 + col]
          + lin_b[col];
    d_x0p[i] = v;
}

// ---------------- init ------------------------------------------------------
__global__ void init_kernel(const float* __restrict__ W_ih,
                            const float* __restrict__ b_ih,
                            const float* __restrict__ b_hh,
                            const float* __restrict__ Wp)
{
    for (int i = blockIdx.x*blockDim.x + threadIdx.x; i < Bc*Hc;
         i += gridDim.x*blockDim.x) {
        d_h[0][i] = 0.f; d_c[i] = 0.f;
        if (i < Cc*Hc) {
            int c = i >> 9, h = i & 511;
            d_WpT[i] = Wp[h*Cc + c];
        }
        if (i < G4) {
            d_wihdur[i] = W_ih[(size_t)i*DP1 + Dc];
            d_bsum[i]   = b_ih[i] + b_hh[i];
        }
    }
}

// ---------------- classifier softmax: logits -> probs -----------------------
__global__ void cls_softmax(const float* __restrict__ bcls)
{
    const int kb = blockIdx.x;            // k*Bc + b
    const int k = kb >> 9;
    const float* row = d_cls + (size_t)kb * Cc;
    float* yr = d_Y + (size_t)kb * Cc;
    int lane = threadIdx.x;
    float v1 = row[lane] + bcls[k*Cc + lane];
    float v2 = (lane + 32 < Cc) ? row[lane + 32] + bcls[k*Cc + lane + 32] : -3.4e38f;
    float m = fmaxf(v1, v2);
    for (int o = 16; o; o >>= 1) m = fmaxf(m, __shfl_xor_sync(0xffffffffu, m, o));
    float e1 = expf(v1 - m);
    float e2 = (lane + 32 < Cc) ? expf(v2 - m) : 0.f;
    float s = e1 + e2;
    for (int o = 16; o; o >>= 1) s += __shfl_xor_sync(0xffffffffu, s, o);
    float inv = 1.f / s;
    yr[lane] = e1 * inv;
    if (lane + 32 < Cc) yr[lane + 32] = e2 * inv;
}

// feat assembly + curr_action + curr_dur + sdur ; one block per b
__global__ void prep_kernel(const float* __restrict__ S, const float* __restrict__ R,
                            const float* __restrict__ dur_W, const float* __restrict__ dur_b,
                            const float* __restrict__ Wdur, float* __restrict__ out)
{
    __shared__ float red[256];
    const int b = blockIdx.x, tid = threadIdx.x;
    float* fr = d_feat + (size_t)b * FEATNP;
    for (int i = tid; i < Kc*Cc; i += 256) {
        int k = i / Cc, c = i - k*Cc;
        fr[i] = d_Y[((size_t)k*Bc + b)*Cc + c];
    }
    for (int i = tid; i < Kc*Dc; i += 256) {
        int k = i >> 10, d = i & 1023;
        fr[Kc*Cc + i]         = S[((size_t)k*Bc + b)*Dc + d];
        fr[Kc*Cc + Kc*Dc + i] = R[((size_t)k*Bc + b)*Dc + d];
    }
    if (tid < FEATNP - FEATN) fr[FEATN + tid] = 0.f;   // zero pad cols
    for (int i = tid; i < Cc; i += 256)
        out[O2 + (size_t)b*Cc + i] = d_Y[(size_t)b*Cc + i]
                                   + d_Y[((size_t)Bc + b)*Cc + i]
                                   + d_Y[((size_t)2*Bc + b)*Cc + i];
    float pd = 0.f;
    for (int i = tid; i < Kc*Dc; i += 256) {
        int k = i >> 10, d = i & 1023;
        pd += R[((size_t)k*Bc + b)*Dc + d] * dur_W[i];
    }
    red[tid] = pd; __syncthreads();
    for (int s = 128; s > 0; s >>= 1) { if (tid < s) red[tid] += red[tid + s]; __syncthreads(); }
    if (tid == 0) out[O3 + (size_t)b*(Tc+1)] = red[0] + dur_b[0];
    __syncthreads();
    for (int k = 0; k < Kc; k++) {
        float ps = 0.f;
        for (int d = tid; d < Dc; d += 256)
            ps += S[((size_t)k*Bc + b)*Dc + d] * Wdur[d];
        red[tid] = ps; __syncthreads();
        for (int s = 128; s > 0; s >>= 1) { if (tid < s) red[tid] += red[tid + s]; __syncthreads(); }
        if (tid == 0) d_sdur[b*Kc + k] = red[0];
        __syncthreads();
    }
}

// fused per-step kernel: LSTM elementwise + logits/probs/argmax + attention +
// dur ; one block per b, 512 threads (16 warps). bsum already folded in GEMMs.
__global__ void __launch_bounds__(512)
step_kernel(const float* __restrict__ S, const float* __restrict__ bp,
            const float* __restrict__ Wdur, const float* __restrict__ bdur,
            float* __restrict__ out, int t, int sel)
{
    __shared__ float sh[Hc];
    __shared__ float slog[Cc];
    __shared__ float sscore[3];
    __shared__ float saw[3];
    __shared__ float sred[16];
    const int b  = blockIdx.x;
    const int th = threadIdx.x;
    const int wid = th >> 5, lane = th & 31;
    const float* h_in = d_h[sel];
    float* h_out = d_h[sel ^ 1];

    float g[4];
    if (t == 0) {
#pragma unroll
        for (int j = 0; j < 4; j++) g[j] = d_gx0[(size_t)b*G4 + j*Hc + th];
    } else {
        int lab = d_labels[b];
        float dp = d_dur[b];
#pragma unroll
        for (int j = 0; j < 4; j++) {
            int gi = j*Hc + th;
            g[j] = d_gates[(size_t)b*G4 + gi] + d_E[(size_t)lab*G4 + gi]
                 + dp * d_wihdur[gi];
        }
    }
    float ig = 1.f / (1.f + expf(-g[0]));
    float fg = 1.f / (1.f + expf(-g[1]));
    float gg = tanhf(g[2]);
    float og = 1.f / (1.f + expf(-g[3]));
    int idx = b*Hc + th;
    float cn = fg * d_c[idx] + ig * gg;
    d_c[idx] = cn;
    float hn = og * tanhf(cn);
    h_out[idx] = hn;
    sh[th] = hn;
    float hp = h_in[idx] * Wdur[Dc + th];
    for (int o = 16; o; o >>= 1) hp += __shfl_xor_sync(0xffffffffu, hp, o);
    if (lane == 0) sred[wid] = hp;
    __syncthreads();

    for (int cc = wid; cc < Cc; cc += 16) {
        float s = 0.f;
        const float* wr = d_WpT + (size_t)cc*Hc;
        for (int j = lane; j < Hc; j += 32) s += sh[j] * wr[j];
        for (int o = 16; o; o >>= 1) s += __shfl_xor_sync(0xffffffffu, s, o);
        if (lane == 0) slog[cc] = s + bp[cc];
    }
    if (wid < 3) {
        float s = 0.f;
        const float* Pr = d_P + ((size_t)wid*Bc + b)*Hc;
        for (int j = lane; j < Hc; j += 32) s += sh[j] * Pr[j];
        for (int o = 16; o; o >>= 1) s += __shfl_xor_sync(0xffffffffu, s, o);
        if (lane == 0) sscore[wid] = s * 0.03125f;  // 1/sqrt(1024)
    }
    __syncthreads();

    if (wid == 0) {
        float v1 = slog[lane];
        float v2 = (lane < Cc - 32) ? slog[32 + lane] : -3.4e38f;
        float m = fmaxf(v1, v2);
        for (int o = 16; o; o >>= 1) m = fmaxf(m, __shfl_xor_sync(0xffffffffu, m, o));
        float e1 = expf(v1 - m);
        float e2 = (lane < Cc - 32) ? expf(v2 - m) : 0.f;
        float s = e1 + e2;
        for (int o = 16; o; o >>= 1) s += __shfl_xor_sync(0xffffffffu, s, o);
        float inv = 1.f / s;
        size_t pb = O1 + ((size_t)b*Tc + t)*Cc;
        out[pb + lane] = e1 * inv;
        if (lane < Cc - 32) out[pb + 32 + lane] = e2 * inv;
        float bv; int bi;
        if (lane < Cc - 32 && v2 > v1) { bv = v2; bi = 32 + lane; }
        else                           { bv = v1; bi = lane; }
        for (int o = 16; o; o >>= 1) {
            float ov = __shfl_xor_sync(0xffffffffu, bv, o);
            int   oi = __shfl_xor_sync(0xffffffffu, bi, o);
            if (ov > bv || (ov == bv && oi < bi)) { bv = ov; bi = oi; }
        }
        float hv = (lane < 16) ? sred[lane] : 0.f;
        for (int o = 8; o; o >>= 1) hv += __shfl_xor_sync(0xffffffffu, hv, o);
        if (lane == 0) {
            out[O0 + (size_t)t*Bc + b] = (float)bi;
            d_labels[b] = bi;
            float s0 = sscore[0], s1 = sscore[1], s2 = sscore[2];
            float sm = fmaxf(s0, fmaxf(s1, s2));
            float a0 = expf(s0 - sm), a1 = expf(s1 - sm), a2 = expf(s2 - sm);
            float z = 1.f / (a0 + a1 + a2);
            a0 *= z; a1 *= z; a2 *= z;
            saw[0] = a0; saw[1] = a1; saw[2] = a2;
            float dur = a0*d_sdur[b*Kc] + a1*d_sdur[b*Kc+1] + a2*d_sdur[b*Kc+2]
                      + hv + bdur[0];
            out[O3 + (size_t)b*(Tc+1) + t + 1] = dur;
            d_dur[b] = dur;
        }
    }
    __syncthreads();

    float a0 = saw[0], a1 = saw[1], a2 = saw[2];
    size_t ab = O4 + ((size_t)t*Bc + b)*Dc;
    const float* S0 = S + (size_t)b*Dc;
    const float* S1 = S + ((size_t)Bc + b)*Dc;
    const float* S2 = S + ((size_t)2*Bc + b)*Dc;
    for (int d = th; d < Dc; d += 512)
        out[ab + d] = a0*S0[d] + a1*S1[d] + a2*S2[d];
}

// ---------------- host ------------------------------------------------------
extern "C" void kernel_launch(void* const* d_in, const int* in_sizes, int n_in,
                              void* d_out, int out_size)
{
    const float* S     = (const float*)d_in[0];
    const float* R     = (const float*)d_in[1];
    const float* cls_W = (const float*)d_in[2];
    const float* cls_b = (const float*)d_in[3];
    const float* dur_W = (const float*)d_in[4];
    const float* dur_b = (const float*)d_in[5];
    const float* lin_W = (const float*)d_in[6];
    const float* lin_b = (const float*)d_in[7];
    const float* W_ih  = (const float*)d_in[8];
    const float* W_hh  = (const float*)d_in[9];
    const float* b_ih  = (const float*)d_in[10];
    const float* b_hh  = (const float*)d_in[11];
    const float* Wp    = (const float*)d_in[12];
    const float* bp    = (const float*)d_in[13];
    const float* Wdur  = (const float*)d_in[14];
    const float* bdur  = (const float*)d_in[15];
    const float* embed = (const float*)d_in[16];
    const float* Wattn = (const float*)d_in[17];
    float* out = (float*)d_out;

    float *pfeat, *px0p, *pxp, *pgx0, *pE, *pEp, *pP, *pgates, *ph, *pbsum;
    float *pWihp, *plinWp, *pcls, *pcWT;
    cudaGetSymbolAddress((void**)&pfeat,  d_feat);
    cudaGetSymbolAddress((void**)&px0p,   d_x0p);
    cudaGetSymbolAddress((void**)&pxp,    d_xp);
    cudaGetSymbolAddress((void**)&pgx0,   d_gx0);
    cudaGetSymbolAddress((void**)&pE,     d_E);
    cudaGetSymbolAddress((void**)&pEp,    d_Ep);
    cudaGetSymbolAddress((void**)&pP,     d_P);
    cudaGetSymbolAddress((void**)&pgates, d_gates);
    cudaGetSymbolAddress((void**)&ph,     d_h);
    cudaGetSymbolAddress((void**)&pbsum,  d_bsum);
    cudaGetSymbolAddress((void**)&pWihp,  d_Wihp);
    cudaGetSymbolAddress((void**)&plinWp, d_linWp);
    cudaGetSymbolAddress((void**)&pcls,   d_cls);
    cudaGetSymbolAddress((void**)&pcWT,   d_cWT);

    init_kernel<<<256, 512>>>(W_ih, b_ih, b_hh, Wp);
    // padded weight copies (zero-filled pads make K-mult-16 loops exact)
    pad_copy<<<512, 256>>>(W_ih,  pWihp,  G4,    DP1, G4,     XP);
    pad_copy<<<1024, 256>>>(lin_W, plinWp, FEATN, DP1, FEATNP, LWP);
    cls_T<<<256, 256>>>(cls_W);

    // classifier logits via tensor GEMM: S-part then R-part (accumulate)
    tgemm<true, false><<<dim3(1, 8, 3), 256>>>(
        S, pcWT, pcls, Bc, Cc, Dc, Dc, D2, Cc, nullptr,
        (long long)Bc*Dc, (long long)Cc*D2, (long long)Bc*Cc);
    tgemm<true, true><<<dim3(1, 8, 3), 256>>>(
        R, pcWT + Dc, pcls, Bc, Cc, Dc, Dc, D2, Cc, nullptr,
        (long long)Bc*Dc, (long long)Cc*D2, (long long)Bc*Cc);
    cls_softmax<<<Kc*Bc, 32>>>(cls_b);
    prep_kernel<<<Bc, 256>>>(S, R, dur_W, dur_b, Wdur, out);

    // x0 = feat @ lin_W + lin_b  [512 x 1025, K=6304]  split-K 2 (144 blocks)
    tgemm<false, false><<<dim3(9, 8, 2), 256>>>(
        pfeat, plinWp, pxp, Bc, DP1, FEATNP/2, FEATNP, LWP, DP1, nullptr,
        (long long)(FEATNP/2), (long long)(FEATNP/2)*LWP, (long long)Bc*DP1);
    reduce_x0<<<(Bc*XP + 255)/256, 256>>>(lin_b);
    // gx0 = x0 @ W_ih^T + bsum  [512 x 2048, K=1040]  (128 blocks)
    tgemm<true, false><<<dim3(16, 8), 256>>>(
        px0p, pWihp, pgx0, Bc, G4, XP, XP, XP, G4, pbsum, 0, 0, 0);
    // E = embed @ W_ih[:, :D]^T  [48 x 2048, K=1024]  split-K 4 (64 blocks)
    tgemm<true, false><<<dim3(16, 1, 4), 256>>>(
        embed, pWihp, pEp, Cc, G4, Dc/4, Dc, XP, G4, nullptr,
        (long long)(Dc/4), (long long)(Dc/4), (long long)Cc*G4);
    reduce_add<<<(Cc*G4 + 255)/256, 256>>>(pEp, pE, Cc*G4, 4, (long long)Cc*G4);
    // P = S_flat @ Wattn^T  [1536 x 512, K=1024]  (96 blocks)
    tgemm<true, false><<<dim3(4, 24), 256>>>(
        S, Wattn, pP, Kc*Bc, Hc, Dc, Dc, Dc, Hc, nullptr, 0, 0, 0);

    int sel = 0;
    for (int t = 0; t < Tc; t++) {
        if (t > 0)
            tgemm<true, false><<<dim3(16, 8), 256>>>(
                ph + (size_t)sel*Bc*Hc, W_hh, pgates,
                Bc, G4, Hc, Hc, Hc, G4, pbsum, 0, 0, 0);
        step_kernel<<<Bc, 512>>>(S, bp, Wdur, bdur, out, t, sel);
        sel ^= 1;
    }
}

// round 14
// speedup vs baseline: 1.1946x; 1.0407x over previous
#include <cuda_runtime.h>
#include <math.h>

#define Kc 3
#define Bc 512
#define Dc 1024
#define Hc 512
#define Cc 48
#define Tc 25
#define G4 2048
#define DP1 1025
#define FEATN 6288
#define FEATNP 6304          // FEATN padded to mult of 16
#define XP 1040              // DP1 padded to mult of 16
#define LWP 1152             // lin_W col pad (9 n-blocks * 128)
#define D2 (2*Dc)
#define CSK 4                // cls split-K factor

// output section offsets (all float32, concatenated in tuple order)
#define O0 0                                  // labels_t   [T,B]
#define O1 (Tc*Bc)                            // probs      [B,T,C]
#define O2 (O1 + Bc*Tc*Cc)                    // curr_action[B,C]
#define O3 (O2 + Bc*Cc)                       // durations  [B,T+1]
#define O4 (O3 + Bc*(Tc+1))                   // att_t      [T,B,D]

// ---------------- scratch (device globals: no allocation allowed) ----------
__device__ float d_clsp[2*Kc*CSK*Bc*Cc];   // classifier split-K partials
__device__ float d_cWT[Kc*Cc*D2];          // cls_W transposed [k][C][2D]
__device__ float d_feat[Bc*FEATNP];
__device__ float d_x0p[Bc*XP];             // x0 padded [512][1040]
__device__ float d_xp[2*Bc*DP1];           // lin split-K partials
__device__ float d_gx0[Bc*G4];             // x0 @ W_ih^T + bsum
__device__ float d_E[Cc*G4];
__device__ float d_Ep[4*Cc*G4];
__device__ float d_P[Kc*Bc*Hc];
__device__ float d_sdur[Bc*Kc];
__device__ float d_gates[Bc*G4];
__device__ float d_h[2][Bc*Hc];
__device__ float d_c[Bc*Hc];
__device__ int   d_labels[Bc];
__device__ float d_dur[Bc];
__device__ float d_WpT[Cc*Hc];
__device__ float d_wihdur[G4];
__device__ float d_bsum[G4];
__device__ float d_Wihp[G4*XP];            // W_ih padded [2048][1040]
__device__ float d_linWp[FEATNP*LWP];      // lin_W padded [6304][1152]
__device__ float d_Whh_hi[G4*Hc];          // W_hh presplit (reused 24x)
__device__ float d_Whh_lo[G4*Hc];

// ---------------- tf32 helpers ----------------------------------------------
__device__ __forceinline__ void tsplit(float x, float &hf, float &lf) {
    unsigned h, l;
    asm("cvt.rna.tf32.f32 %0, %1;" : "=r"(h) : "f"(x));
    hf = __uint_as_float(h);
    float r = x - hf;
    asm("cvt.rna.tf32.f32 %0, %1;" : "=r"(l) : "f"(r));
    lf = __uint_as_float(l);
}
__device__ __forceinline__ void ldm4(unsigned* r, unsigned addr) {
    asm volatile("ldmatrix.sync.aligned.m8n8.x4.shared.b16 {%0,%1,%2,%3}, [%4];"
        : "=r"(r[0]), "=r"(r[1]), "=r"(r[2]), "=r"(r[3]) : "r"(addr));
}
__device__ __forceinline__ void mma8(float* c, const unsigned* a, const unsigned* b) {
    asm volatile("mma.sync.aligned.m16n8k8.row.col.f32.tf32.tf32.f32 "
        "{%0,%1,%2,%3},{%4,%5,%6,%7},{%8,%9},{%0,%1,%2,%3};"
        : "+f"(c[0]), "+f"(c[1]), "+f"(c[2]), "+f"(c[3])
        : "r"(a[0]), "r"(a[1]), "r"(a[2]), "r"(a[3]), "r"(b[0]), "r"(b[1]));
}
// swizzled word index of 16B chunk start (row stride 20 f32, 4 data chunks)
__device__ __forceinline__ int swz(int row, int chunk) {
    return row*20 + (((chunk ^ (row >> 3)) & 3) << 2);
}

// ---------------- tgemm: 64x128 tile, 3xTF32, NT/NN, split-K -----------------
// C[m,n] = sum_k A[m,k]*B'[k,n] (+bias[n]).  256 thr, KSTEP=16.
// BT=true : B is [N,K] row-major;  BT=false: B is [K,N] row-major.
// blockIdx.z = batch*SK + s: batch advances A/B by sA/sB; s advances K-window
// by s*K; C advances by z*sC (each split writes its own partial buffer).
template<bool BT, int SK>
__global__ void __launch_bounds__(256)
tgemm(const float* __restrict__ A, const float* __restrict__ Bm,
      float* __restrict__ C, int M, int N, int K,
      int lda, int ldb, int ldc, const float* __restrict__ bias,
      long long sA, long long sB, long long sC)
{
    __shared__ __align__(16) float As_hi[64*20], As_lo[64*20];
    __shared__ __align__(16) float Bs_hi[128*20], Bs_lo[128*20];

    {
        const int z = blockIdx.z, bt = z / SK, s = z % SK;
        A  += (size_t)bt * sA + (size_t)s * K;
        if (BT) Bm += (size_t)bt * sB + (size_t)s * K;
        else    Bm += (size_t)bt * sB + (size_t)s * K * ldb;
        C  += (size_t)z * sC;
    }

    const int tid  = threadIdx.x;
    const int lane = tid & 31, wid = tid >> 5;
    const int m0 = blockIdx.y * 64, n0 = blockIdx.x * 128;
    const int am = (wid & 1) * 32;
    const int an = (wid >> 1) * 32;

    const unsigned aH = (unsigned)__cvta_generic_to_shared(As_hi);
    const unsigned aL = (unsigned)__cvta_generic_to_shared(As_lo);
    const unsigned bH = (unsigned)__cvta_generic_to_shared(Bs_hi);
    const unsigned bL = (unsigned)__cvta_generic_to_shared(Bs_lo);

    float acc[2][4][4];
#pragma unroll
    for (int i = 0; i < 2; i++)
#pragma unroll
        for (int j = 0; j < 4; j++)
#pragma unroll
            for (int q = 0; q < 4; q++) acc[i][j][q] = 0.f;

    for (int k0 = 0; k0 < K; k0 += 16) {
        float4 va = make_float4(0.f, 0.f, 0.f, 0.f);
        {
            int row = tid >> 2, kq = tid & 3;
            if (m0 + row < M)
                va = *(const float4*)&A[(size_t)(m0+row)*lda + k0 + 4*kq];
        }
        float4 vb0 = make_float4(0.f,0.f,0.f,0.f), vb1 = vb0;
        if (BT) {
            int n = tid >> 1, h8 = (tid & 1) * 8;
            if (n0 + n < N) {
                const float* src = &Bm[(size_t)(n0+n)*ldb + k0 + h8];
                vb0 = *(const float4*)src;
                vb1 = *(const float4*)(src + 4);
            }
        } else {
            int k = tid >> 4, nq = tid & 15;
            const float* src = &Bm[(size_t)(k0+k)*ldb + n0 + 8*nq];
            vb0 = *(const float4*)src;
            vb1 = *(const float4*)(src + 4);
        }
        __syncthreads();
        {
            int row = tid >> 2, kq = tid & 3;
            float4 h4, l4;
            tsplit(va.x, h4.x, l4.x); tsplit(va.y, h4.y, l4.y);
            tsplit(va.z, h4.z, l4.z); tsplit(va.w, h4.w, l4.w);
            int w = swz(row, kq);
            *(float4*)&As_hi[w] = h4;
            *(float4*)&As_lo[w] = l4;
        }
        if (BT) {
            int n = tid >> 1, cb = (tid & 1) * 2;
            float4 h4, l4;
            tsplit(vb0.x, h4.x, l4.x); tsplit(vb0.y, h4.y, l4.y);
            tsplit(vb0.z, h4.z, l4.z); tsplit(vb0.w, h4.w, l4.w);
            int w = swz(n, cb);
            *(float4*)&Bs_hi[w] = h4; *(float4*)&Bs_lo[w] = l4;
            tsplit(vb1.x, h4.x, l4.x); tsplit(vb1.y, h4.y, l4.y);
            tsplit(vb1.z, h4.z, l4.z); tsplit(vb1.w, h4.w, l4.w);
            w = swz(n, cb + 1);
            *(float4*)&Bs_hi[w] = h4; *(float4*)&Bs_lo[w] = l4;
        } else {
            int k = tid >> 4, nq = tid & 15;
            const float* p0 = (const float*)&vb0;
            const float* p1 = (const float*)&vb1;
#pragma unroll
            for (int e = 0; e < 4; e++) {
                float hv, lv;
                int nl = 8*nq + e;
                int w = swz(nl, k >> 2) + (k & 3);
                tsplit(p0[e], hv, lv); Bs_hi[w] = hv; Bs_lo[w] = lv;
                nl += 4; w = swz(nl, k >> 2) + (k & 3);
                tsplit(p1[e], hv, lv); Bs_hi[w] = hv; Bs_lo[w] = lv;
            }
        }
        __syncthreads();
#pragma unroll
        for (int half = 0; half < 2; half++) {
            const int kc = half * 8;
            unsigned ah[2][4], al[2][4], bh[4][2], bl[4][2];
#pragma unroll
            for (int i = 0; i < 2; i++) {
                int row = am + 16*i + (lane & 15);
                int chunk = (kc >> 2) + (lane >> 4);
                unsigned off = 4u * (unsigned)swz(row, chunk);
                ldm4(ah[i], aH + off);
                ldm4(al[i], aL + off);
            }
#pragma unroll
            for (int g = 0; g < 2; g++) {
                int row = an + 16*g + (lane & 7) + ((lane >> 4) << 3);
                int chunk = (kc >> 2) + ((lane >> 3) & 1);
                unsigned off = 4u * (unsigned)swz(row, chunk);
                unsigned r[4];
                ldm4(r, bH + off);
                bh[2*g][0] = r[0]; bh[2*g][1] = r[1];
                bh[2*g+1][0] = r[2]; bh[2*g+1][1] = r[3];
                ldm4(r, bL + off);
                bl[2*g][0] = r[0]; bl[2*g][1] = r[1];
                bl[2*g+1][0] = r[2]; bl[2*g+1][1] = r[3];
            }
#pragma unroll
            for (int i = 0; i < 2; i++)
#pragma unroll
                for (int j = 0; j < 4; j++) {
                    mma8(acc[i][j], ah[i], bh[j]);
                    mma8(acc[i][j], ah[i], bl[j]);
                    mma8(acc[i][j], al[i], bh[j]);
                }
        }
    }

#pragma unroll
    for (int i = 0; i < 2; i++) {
#pragma unroll
        for (int j = 0; j < 4; j++) {
            int r0 = m0 + am + 16*i + (lane >> 2);
            int c0 = n0 + an + 8*j + (lane & 3) * 2;
            float b0 = 0.f, b1 = 0.f;
            if (bias) {
                if (c0 < N)     b0 = bias[c0];
                if (c0 + 1 < N) b1 = bias[c0 + 1];
            }
            if (r0 < M) {
                float* p = &C[(size_t)r0*ldc + c0];
                if (c0 < N)     p[0] = acc[i][j][0] + b0;
                if (c0 + 1 < N) p[1] = acc[i][j][1] + b1;
            }
            if (r0 + 8 < M) {
                float* p = &C[(size_t)(r0+8)*ldc + c0];
                if (c0 < N)     p[0] = acc[i][j][2] + b0;
                if (c0 + 1 < N) p[1] = acc[i][j][3] + b1;
            }
        }
    }
}

// ---------------- tgemmps: rec gemm with PRESPLIT B (W_hh hi/lo) ------------
// Same tile/layout as tgemm<true,1>; B loader is pure LDG->STS.
__global__ void __launch_bounds__(256)
tgemmps(const float* __restrict__ A,
        const float* __restrict__ Bhi, const float* __restrict__ Blo,
        float* __restrict__ C, int M, int N, int K,
        int lda, int ldb, int ldc, const float* __restrict__ bias)
{
    __shared__ __align__(16) float As_hi[64*20], As_lo[64*20];
    __shared__ __align__(16) float Bs_hi[128*20], Bs_lo[128*20];

    const int tid  = threadIdx.x;
    const int lane = tid & 31, wid = tid >> 5;
    const int m0 = blockIdx.y * 64, n0 = blockIdx.x * 128;
    const int am = (wid & 1) * 32;
    const int an = (wid >> 1) * 32;

    const unsigned aH = (unsigned)__cvta_generic_to_shared(As_hi);
    const unsigned aL = (unsigned)__cvta_generic_to_shared(As_lo);
    const unsigned bH = (unsigned)__cvta_generic_to_shared(Bs_hi);
    const unsigned bL = (unsigned)__cvta_generic_to_shared(Bs_lo);

    float acc[2][4][4];
#pragma unroll
    for (int i = 0; i < 2; i++)
#pragma unroll
        for (int j = 0; j < 4; j++)
#pragma unroll
            for (int q = 0; q < 4; q++) acc[i][j][q] = 0.f;

    for (int k0 = 0; k0 < K; k0 += 16) {
        float4 va = make_float4(0.f, 0.f, 0.f, 0.f);
        {
            int row = tid >> 2, kq = tid & 3;
            va = *(const float4*)&A[(size_t)(m0+row)*lda + k0 + 4*kq];
        }
        int bn = tid >> 1, bh8 = (tid & 1) * 8;
        size_t boff = (size_t)(n0+bn)*ldb + k0 + bh8;
        float4 vh0 = *(const float4*)&Bhi[boff];
        float4 vh1 = *(const float4*)&Bhi[boff + 4];
        float4 vl0 = *(const float4*)&Blo[boff];
        float4 vl1 = *(const float4*)&Blo[boff + 4];
        __syncthreads();
        {
            int row = tid >> 2, kq = tid & 3;
            float4 h4, l4;
            tsplit(va.x, h4.x, l4.x); tsplit(va.y, h4.y, l4.y);
            tsplit(va.z, h4.z, l4.z); tsplit(va.w, h4.w, l4.w);
            int w = swz(row, kq);
            *(float4*)&As_hi[w] = h4;
            *(float4*)&As_lo[w] = l4;
        }
        {
            int cb = (tid & 1) * 2;
            int w = swz(bn, cb);
            *(float4*)&Bs_hi[w] = vh0; *(float4*)&Bs_lo[w] = vl0;
            w = swz(bn, cb + 1);
            *(float4*)&Bs_hi[w] = vh1; *(float4*)&Bs_lo[w] = vl1;
        }
        __syncthreads();
#pragma unroll
        for (int half = 0; half < 2; half++) {
            const int kc = half * 8;
            unsigned ah[2][4], al[2][4], bh[4][2], bl[4][2];
#pragma unroll
            for (int i = 0; i < 2; i++) {
                int row = am + 16*i + (lane & 15);
                int chunk = (kc >> 2) + (lane >> 4);
                unsigned off = 4u * (unsigned)swz(row, chunk);
                ldm4(ah[i], aH + off);
                ldm4(al[i], aL + off);
            }
#pragma unroll
            for (int g = 0; g < 2; g++) {
                int row = an + 16*g + (lane & 7) + ((lane >> 4) << 3);
                int chunk = (kc >> 2) + ((lane >> 3) & 1);
                unsigned off = 4u * (unsigned)swz(row, chunk);
                unsigned r[4];
                ldm4(r, bH + off);
                bh[2*g][0] = r[0]; bh[2*g][1] = r[1];
                bh[2*g+1][0] = r[2]; bh[2*g+1][1] = r[3];
                ldm4(r, bL + off);
                bl[2*g][0] = r[0]; bl[2*g][1] = r[1];
                bl[2*g+1][0] = r[2]; bl[2*g+1][1] = r[3];
            }
#pragma unroll
            for (int i = 0; i < 2; i++)
#pragma unroll
                for (int j = 0; j < 4; j++) {
                    mma8(acc[i][j], ah[i], bh[j]);
                    mma8(acc[i][j], ah[i], bl[j]);
                    mma8(acc[i][j], al[i], bh[j]);
                }
        }
    }

#pragma unroll
    for (int i = 0; i < 2; i++) {
#pragma unroll
        for (int j = 0; j < 4; j++) {
            int r0 = m0 + am + 16*i + (lane >> 2);
            int c0 = n0 + an + 8*j + (lane & 3) * 2;
            float b0 = bias[c0], b1 = bias[c0 + 1];
            float* p = &C[(size_t)r0*ldc + c0];
            p[0] = acc[i][j][0] + b0;
            p[1] = acc[i][j][1] + b1;
            p = &C[(size_t)(r0+8)*ldc + c0];
            p[0] = acc[i][j][2] + b0;
            p[1] = acc[i][j][3] + b1;
        }
    }
}

// ---------------- mega init: state + pads + transposes + Whh presplit -------
__global__ void mega_init(const float* __restrict__ W_ih,
                          const float* __restrict__ b_ih,
                          const float* __restrict__ b_hh,
                          const float* __restrict__ Wp,
                          const float* __restrict__ lin_W,
                          const float* __restrict__ cls_W,
                          const float* __restrict__ W_hh)
{
    const long long gs = (long long)gridDim.x * blockDim.x;
    const long long id = (long long)blockIdx.x * blockDim.x + threadIdx.x;
    for (long long i = id; i < Bc*Hc; i += gs) { d_h[0][i] = 0.f; d_c[i] = 0.f; }
    for (long long i = id; i < Cc*Hc; i += gs) {
        int c = (int)(i >> 9), h = (int)(i & 511);
        d_WpT[i] = Wp[h*Cc + c];
    }
    for (long long i = id; i < G4; i += gs) {
        d_wihdur[i] = W_ih[(size_t)i*DP1 + Dc];
        d_bsum[i]   = b_ih[i] + b_hh[i];
    }
    for (long long i = id; i < (long long)G4*XP; i += gs) {
        int r = (int)(i / XP), c = (int)(i % XP);
        d_Wihp[i] = (c < DP1) ? W_ih[(size_t)r*DP1 + c] : 0.f;
    }
    for (long long i = id; i < (long long)FEATNP*LWP; i += gs) {
        int r = (int)(i / LWP), c = (int)(i % LWP);
        d_linWp[i] = (r < FEATN && c < DP1) ? lin_W[(size_t)r*DP1 + c] : 0.f;
    }
    for (long long i = id; i < (long long)Kc*D2*Cc; i += gs) {
        int k = (int)(i / (D2*Cc)), rem = (int)(i % (D2*Cc));
        int d = rem / Cc, c = rem % Cc;
        d_cWT[(size_t)k*Cc*D2 + (size_t)c*D2 + d] = cls_W[i];
    }
    for (long long i = id; i < (long long)G4*Hc; i += gs) {
        float h, l; tsplit(W_hh[i], h, l);
        d_Whh_hi[i] = h; d_Whh_lo[i] = l;
    }
}

// ---------------- split-K reduce (E) + padded reduce (x0) -------------------
__global__ void reduce_add(const float* __restrict__ part, float* __restrict__ outp,
                           int n, int nparts, long long stride)
{
    int i = blockIdx.x * blockDim.x + threadIdx.x;
    if (i >= n) return;
    float s = 0.f;
    for (int z = 0; z < nparts; z++) s += part[(size_t)z*stride + i];
    outp[i] = s;
}

__global__ void reduce_x0(const float* __restrict__ lin_b)
{
    int i = blockIdx.x * blockDim.x + threadIdx.x;
    if (i >= Bc*XP) return;
    int row = i / XP, col = i % XP;
    float v = 0.f;
    if (col < DP1)
        v = d_xp[(size_t)row*DP1 + col] + d_xp[(size_t)Bc*DP1 + (size_t)row*DP1 + col]
          + lin_b[col];
    d_x0p[i] = v;
}

// ---------------- prep: cls reduce+softmax, feat, curr_action, durs ---------
__global__ void prep_kernel(const float* __restrict__ S, const float* __restrict__ R,
                            const float* __restrict__ dur_W, const float* __restrict__ dur_b,
                            const float* __restrict__ Wdur, const float* __restrict__ bcls,
                            float* __restrict__ out)
{
    __shared__ float red[256];
    __shared__ float sY[Kc][Cc];
    const int b = blockIdx.x, tid = threadIdx.x;
    const int wid = tid >> 5, lane = tid & 31;

    // classifier: reduce 2*CSK partials + bias, softmax over 48 (3 warps)
    if (wid < Kc) {
        const int k = wid;
        float v1 = bcls[k*Cc + lane];
        float v2 = (lane < 16) ? bcls[k*Cc + lane + 32] : -3.4e38f;
#pragma unroll
        for (int j = 0; j < CSK; j++) {
            size_t o1 = (size_t)(k*CSK + j)*(Bc*Cc) + (size_t)b*Cc;
            size_t o2 = (size_t)(Kc*CSK + k*CSK + j)*(Bc*Cc) + (size_t)b*Cc;
            v1 += d_clsp[o1 + lane] + d_clsp[o2 + lane];
            if (lane < 16) v2 += d_clsp[o1 + lane + 32] + d_clsp[o2 + lane + 32];
        }
        float m = fmaxf(v1, v2);
        for (int o = 16; o; o >>= 1) m = fmaxf(m, __shfl_xor_sync(0xffffffffu, m, o));
        float e1 = expf(v1 - m);
        float e2 = (lane < 16) ? expf(v2 - m) : 0.f;
        float s = e1 + e2;
        for (int o = 16; o; o >>= 1) s += __shfl_xor_sync(0xffffffffu, s, o);
        float inv = 1.f / s;
        sY[k][lane] = e1 * inv;
        if (lane < 16) sY[k][lane + 32] = e2 * inv;
    }
    __syncthreads();

    float* fr = d_feat + (size_t)b * FEATNP;
    for (int i = tid; i < Kc*Cc; i += 256) {
        int k = i / Cc, c = i - k*Cc;
        fr[i] = sY[k][c];
    }
    for (int i = tid; i < Kc*Dc; i += 256) {
        int k = i >> 10, d = i & 1023;
        fr[Kc*Cc + i]         = S[((size_t)k*Bc + b)*Dc + d];
        fr[Kc*Cc + Kc*Dc + i] = R[((size_t)k*Bc + b)*Dc + d];
    }
    if (tid < FEATNP - FEATN) fr[FEATN + tid] = 0.f;   // zero pad cols
    for (int i = tid; i < Cc; i += 256)
        out[O2 + (size_t)b*Cc + i] = sY[0][i] + sY[1][i] + sY[2][i];
    float pd = 0.f;
    for (int i = tid; i < Kc*Dc; i += 256) {
        int k = i >> 10, d = i & 1023;
        pd += R[((size_t)k*Bc + b)*Dc + d] * dur_W[i];
    }
    red[tid] = pd; __syncthreads();
    for (int s = 128; s > 0; s >>= 1) { if (tid < s) red[tid] += red[tid + s]; __syncthreads(); }
    if (tid == 0) out[O3 + (size_t)b*(Tc+1)] = red[0] + dur_b[0];
    __syncthreads();
    for (int k = 0; k < Kc; k++) {
        float ps = 0.f;
        for (int d = tid; d < Dc; d += 256)
            ps += S[((size_t)k*Bc + b)*Dc + d] * Wdur[d];
        red[tid] = ps; __syncthreads();
        for (int s = 128; s > 0; s >>= 1) { if (tid < s) red[tid] += red[tid + s]; __syncthreads(); }
        if (tid == 0) d_sdur[b*Kc + k] = red[0];
        __syncthreads();
    }
}

// fused per-step kernel: LSTM elementwise + logits/probs/argmax + attention +
// dur ; one block per b, 512 threads (16 warps). bsum already folded in GEMMs.
__global__ void __launch_bounds__(512)
step_kernel(const float* __restrict__ S, const float* __restrict__ bp,
            const float* __restrict__ Wdur, const float* __restrict__ bdur,
            float* __restrict__ out, int t, int sel)
{
    __shared__ float sh[Hc];
    __shared__ float slog[Cc];
    __shared__ float sscore[3];
    __shared__ float saw[3];
    __shared__ float sred[16];
    const int b  = blockIdx.x;
    const int th = threadIdx.x;
    const int wid = th >> 5, lane = th & 31;
    const float* h_in = d_h[sel];
    float* h_out = d_h[sel ^ 1];

    float g[4];
    if (t == 0) {
#pragma unroll
        for (int j = 0; j < 4; j++) g[j] = d_gx0[(size_t)b*G4 + j*Hc + th];
    } else {
        int lab = d_labels[b];
        float dp = d_dur[b];
#pragma unroll
        for (int j = 0; j < 4; j++) {
            int gi = j*Hc + th;
            g[j] = d_gates[(size_t)b*G4 + gi] + d_E[(size_t)lab*G4 + gi]
                 + dp * d_wihdur[gi];
        }
    }
    float ig = 1.f / (1.f + expf(-g[0]));
    float fg = 1.f / (1.f + expf(-g[1]));
    float gg = tanhf(g[2]);
    float og = 1.f / (1.f + expf(-g[3]));
    int idx = b*Hc + th;
    float cn = fg * d_c[idx] + ig * gg;
    d_c[idx] = cn;
    float hn = og * tanhf(cn);
    h_out[idx] = hn;
    sh[th] = hn;
    float hp = h_in[idx] * Wdur[Dc + th];
    for (int o = 16; o; o >>= 1) hp += __shfl_xor_sync(0xffffffffu, hp, o);
    if (lane == 0) sred[wid] = hp;
    __syncthreads();

    for (int cc = wid; cc < Cc; cc += 16) {
        float s = 0.f;
        const float* wr = d_WpT + (size_t)cc*Hc;
        for (int j = lane; j < Hc; j += 32) s += sh[j] * wr[j];
        for (int o = 16; o; o >>= 1) s += __shfl_xor_sync(0xffffffffu, s, o);
        if (lane == 0) slog[cc] = s + bp[cc];
    }
    if (wid < 3) {
        float s = 0.f;
        const float* Pr = d_P + ((size_t)wid*Bc + b)*Hc;
        for (int j = lane; j < Hc; j += 32) s += sh[j] * Pr[j];
        for (int o = 16; o; o >>= 1) s += __shfl_xor_sync(0xffffffffu, s, o);
        if (lane == 0) sscore[wid] = s * 0.03125f;  // 1/sqrt(1024)
    }
    __syncthreads();

    if (wid == 0) {
        float v1 = slog[lane];
        float v2 = (lane < Cc - 32) ? slog[32 + lane] : -3.4e38f;
        float m = fmaxf(v1, v2);
        for (int o = 16; o; o >>= 1) m = fmaxf(m, __shfl_xor_sync(0xffffffffu, m, o));
        float e1 = expf(v1 - m);
        float e2 = (lane < Cc - 32) ? expf(v2 - m) : 0.f;
        float s = e1 + e2;
        for (int o = 16; o; o >>= 1) s += __shfl_xor_sync(0xffffffffu, s, o);
        float inv = 1.f / s;
        size_t pb = O1 + ((size_t)b*Tc + t)*Cc;
        out[pb + lane] = e1 * inv;
        if (lane < Cc - 32) out[pb + 32 + lane] = e2 * inv;
        float bv; int bi;
        if (lane < Cc - 32 && v2 > v1) { bv = v2; bi = 32 + lane; }
        else                           { bv = v1; bi = lane; }
        for (int o = 16; o; o >>= 1) {
            float ov = __shfl_xor_sync(0xffffffffu, bv, o);
            int   oi = __shfl_xor_sync(0xffffffffu, bi, o);
            if (ov > bv || (ov == bv && oi < bi)) { bv = ov; bi = oi; }
        }
        float hv = (lane < 16) ? sred[lane] : 0.f;
        for (int o = 8; o; o >>= 1) hv += __shfl_xor_sync(0xffffffffu, hv, o);
        if (lane == 0) {
            out[O0 + (size_t)t*Bc + b] = (float)bi;
            d_labels[b] = bi;
            float s0 = sscore[0], s1 = sscore[1], s2 = sscore[2];
            float sm = fmaxf(s0, fmaxf(s1, s2));
            float a0 = expf(s0 - sm), a1 = expf(s1 - sm), a2 = expf(s2 - sm);
            float z = 1.f / (a0 + a1 + a2);
            a0 *= z; a1 *= z; a2 *= z;
            saw[0] = a0; saw[1] = a1; saw[2] = a2;
            float dur = a0*d_sdur[b*Kc] + a1*d_sdur[b*Kc+1] + a2*d_sdur[b*Kc+2]
                      + hv + bdur[0];
            out[O3 + (size_t)b*(Tc+1) + t + 1] = dur;
            d_dur[b] = dur;
        }
    }
    __syncthreads();

    float a0 = saw[0], a1 = saw[1], a2 = saw[2];
    size_t ab = O4 + ((size_t)t*Bc + b)*Dc;
    const float* S0 = S + (size_t)b*Dc;
    const float* S1 = S + ((size_t)Bc + b)*Dc;
    const float* S2 = S + ((size_t)2*Bc + b)*Dc;
    for (int d = th; d < Dc; d += 512)
        out[ab + d] = a0*S0[d] + a1*S1[d] + a2*S2[d];
}

// ---------------- host ------------------------------------------------------
extern "C" void kernel_launch(void* const* d_in, const int* in_sizes, int n_in,
                              void* d_out, int out_size)
{
    const float* S     = (const float*)d_in[0];
    const float* R     = (const float*)d_in[1];
    const float* cls_W = (const float*)d_in[2];
    const float* cls_b = (const float*)d_in[3];
    const float* dur_W = (const float*)d_in[4];
    const float* dur_b = (const float*)d_in[5];
    const float* lin_W = (const float*)d_in[6];
    const float* lin_b = (const float*)d_in[7];
    const float* W_ih  = (const float*)d_in[8];
    const float* W_hh  = (const float*)d_in[9];
    const float* b_ih  = (const float*)d_in[10];
    const float* b_hh  = (const float*)d_in[11];
    const float* Wp    = (const float*)d_in[12];
    const float* bp    = (const float*)d_in[13];
    const float* Wdur  = (const float*)d_in[14];
    const float* bdur  = (const float*)d_in[15];
    const float* embed = (const float*)d_in[16];
    const float* Wattn = (const float*)d_in[17];
    float* out = (float*)d_out;

    float *pfeat, *px0p, *pxp, *pgx0, *pE, *pEp, *pP, *pgates, *ph, *pbsum;
    float *pWihp, *plinWp, *pclsp, *pcWT, *pWhh_hi, *pWhh_lo;
    cudaGetSymbolAddress((void**)&pfeat,   d_feat);
    cudaGetSymbolAddress((void**)&px0p,    d_x0p);
    cudaGetSymbolAddress((void**)&pxp,     d_xp);
    cudaGetSymbolAddress((void**)&pgx0,    d_gx0);
    cudaGetSymbolAddress((void**)&pE,      d_E);
    cudaGetSymbolAddress((void**)&pEp,     d_Ep);
    cudaGetSymbolAddress((void**)&pP,      d_P);
    cudaGetSymbolAddress((void**)&pgates,  d_gates);
    cudaGetSymbolAddress((void**)&ph,      d_h);
    cudaGetSymbolAddress((void**)&pbsum,   d_bsum);
    cudaGetSymbolAddress((void**)&pWihp,   d_Wihp);
    cudaGetSymbolAddress((void**)&plinWp,  d_linWp);
    cudaGetSymbolAddress((void**)&pclsp,   d_clsp);
    cudaGetSymbolAddress((void**)&pcWT,    d_cWT);
    cudaGetSymbolAddress((void**)&pWhh_hi, d_Whh_hi);
    cudaGetSymbolAddress((void**)&pWhh_lo, d_Whh_lo);

    mega_init<<<1024, 256>>>(W_ih, b_ih, b_hh, Wp, lin_W, cls_W, W_hh);

    // P = S_flat @ Wattn^T  [1536 x 512, K=1024]  (96 blocks, early for ncu)
    tgemm<true, 1><<<dim3(4, 24), 256>>>(
        S, Wattn, pP, Kc*Bc, Hc, Dc, Dc, Dc, Hc, nullptr, 0, 0, 0);

    // classifier logits: split-K 4 per (k, S/R part) -> partial buffers
    tgemm<true, CSK><<<dim3(1, 8, Kc*CSK), 256>>>(
        S, pcWT, pclsp, Bc, Cc, Dc/CSK, Dc, D2, Cc, nullptr,
        (long long)Bc*Dc, (long long)Cc*D2, (long long)Bc*Cc);
    tgemm<true, CSK><<<dim3(1, 8, Kc*CSK), 256>>>(
        R, pcWT + Dc, pclsp + (size_t)Kc*CSK*Bc*Cc, Bc, Cc, Dc/CSK, Dc, D2, Cc,
        nullptr, (long long)Bc*Dc, (long long)Cc*D2, (long long)Bc*Cc);

    prep_kernel<<<Bc, 256>>>(S, R, dur_W, dur_b, Wdur, cls_b, out);

    // x0 = feat @ lin_W + lin_b  [512 x 1025, K=6304]  split-K 2 (144 blocks)
    tgemm<false, 2><<<dim3(9, 8, 2), 256>>>(
        pfeat, plinWp, pxp, Bc, DP1, FEATNP/2, FEATNP, LWP, DP1, nullptr,
        0, 0, (long long)Bc*DP1);
    reduce_x0<<<(Bc*XP + 255)/256, 256>>>(lin_b);
    // gx0 = x0 @ W_ih^T + bsum  [512 x 2048, K=1040]  (128 blocks)
    tgemm<true, 1><<<dim3(16, 8), 256>>>(
        px0p, pWihp, pgx0, Bc, G4, XP, XP, XP, G4, pbsum, 0, 0, 0);
    // E = embed @ W_ih[:, :D]^T  [48 x 2048, K=1024]  split-K 4 (64 blocks)
    tgemm<true, 4><<<dim3(16, 1, 4), 256>>>(
        embed, pWihp, pEp, Cc, G4, Dc/4, Dc, XP, G4, nullptr,
        0, 0, (long long)Cc*G4);
    reduce_add<<<(Cc*G4 + 255)/256, 256>>>(pEp, pE, Cc*G4, 4, (long long)Cc*G4);

    int sel = 0;
    for (int t = 0; t < Tc; t++) {
        if (t > 0)
            tgemmps<<<dim3(16, 8), 256>>>(
                ph + (size_t)sel*Bc*Hc, pWhh_hi, pWhh_lo, pgates,
                Bc, G4, Hc, Hc, Hc, G4, pbsum);
        step_kernel<<<Bc, 512>>>(S, bp, Wdur, bdur, out, t, sel);
        sel ^= 1;
    }
}

// round 17
// speedup vs baseline: 1.4276x; 1.1951x over previous
#include <cuda_runtime.h>
#include <math.h>

#define Kc 3
#define Bc 512
#define Dc 1024
#define Hc 512
#define Cc 48
#define Tc 25
#define G4 2048
#define DP1 1025
#define FEATN 6288
#define FEATNP 6304          // FEATN padded to mult of 16
#define XP 1040              // DP1 padded to mult of 16
#define LWP 1152             // lin_W col pad (9 n-blocks * 128)
#define D2 (2*Dc)
#define CSK 4                // cls split-K factor

// output section offsets (all float32, concatenated in tuple order)
#define O0 0                                  // labels_t   [T,B]
#define O1 (Tc*Bc)                            // probs      [B,T,C]
#define O2 (O1 + Bc*Tc*Cc)                    // curr_action[B,C]
#define O3 (O2 + Bc*Cc)                       // durations  [B,T+1]
#define O4 (O3 + Bc*(Tc+1))                   // att_t      [T,B,D]

// ---------------- scratch (device globals: no allocation allowed) ----------
__device__ float d_clsp[2*Kc*CSK*Bc*Cc];   // classifier split-K partials
__device__ float d_cWT[Kc*Cc*D2];          // cls_W transposed [k][C][2D]
__device__ float d_feat[Bc*FEATNP];
__device__ float d_x0p[Bc*XP];             // x0 padded [512][1040]
__device__ float d_xp[2*Bc*DP1];           // lin split-K partials
__device__ float d_gx0[Bc*G4];             // x0 @ W_ih^T + bsum
__device__ float d_E[Cc*G4];
__device__ float d_Ep[4*Cc*G4];
__device__ float d_P[Kc*Bc*Hc];
__device__ float d_sdur[Bc*Kc];
__device__ float d_gates[Bc*G4];
__device__ float d_h[2][Bc*Hc];
__device__ float d_c[Bc*Hc];
__device__ int   d_labels[Bc];
__device__ float d_dur[Bc];
__device__ float d_WpT[Cc*Hc];
__device__ float d_wihdur[G4];
__device__ float d_bsum[G4];
__device__ float d_Wihp[G4*XP];            // W_ih padded [2048][1040]
__device__ float d_linWp[FEATNP*LWP];      // lin_W padded [6304][1152]
__device__ float d_Whh_hi[G4*Hc];          // W_hh presplit (reused 24x)
__device__ float d_Whh_lo[G4*Hc];

// ---------------- tf32 helpers ----------------------------------------------
__device__ __forceinline__ void tsplit(float x, float &hf, float &lf) {
    unsigned h, l;
    asm("cvt.rna.tf32.f32 %0, %1;" : "=r"(h) : "f"(x));
    hf = __uint_as_float(h);
    float r = x - hf;
    asm("cvt.rna.tf32.f32 %0, %1;" : "=r"(l) : "f"(r));
    lf = __uint_as_float(l);
}
__device__ __forceinline__ void ldm4(unsigned* r, unsigned addr) {
    asm volatile("ldmatrix.sync.aligned.m8n8.x4.shared.b16 {%0,%1,%2,%3}, [%4];"
        : "=r"(r[0]), "=r"(r[1]), "=r"(r[2]), "=r"(r[3]) : "r"(addr));
}
__device__ __forceinline__ void mma8(float* c, const unsigned* a, const unsigned* b) {
    asm volatile("mma.sync.aligned.m16n8k8.row.col.f32.tf32.tf32.f32 "
        "{%0,%1,%2,%3},{%4,%5,%6,%7},{%8,%9},{%0,%1,%2,%3};"
        : "+f"(c[0]), "+f"(c[1]), "+f"(c[2]), "+f"(c[3])
        : "r"(a[0]), "r"(a[1]), "r"(a[2]), "r"(a[3]), "r"(b[0]), "r"(b[1]));
}
// swizzled word index of 16B chunk start (row stride 20 f32, 4 data chunks)
__device__ __forceinline__ int swz(int row, int chunk) {
    return row*20 + (((chunk ^ (row >> 3)) & 3) << 2);
}

// ---------------- tgemm: 64x128 tile, 3xTF32, NT/NN, split-K, prefetched ----
// C[m,n] = sum_k A[m,k]*B'[k,n] (+bias[n]).  256 thr, KSTEP=16.
// Chunk loop is software-pipelined: LDGs for chunk ch+1 issue before the MMA
// work of chunk ch, hiding global latency behind tensor-core compute.
// BT=true : B is [N,K] row-major;  BT=false: B is [K,N] row-major.
// blockIdx.z = batch*SK + s (split-K windows write separate partial buffers).
template<bool BT, int SK>
__global__ void __launch_bounds__(256)
tgemm(const float* __restrict__ A, const float* __restrict__ Bm,
      float* __restrict__ C, int M, int N, int K,
      int lda, int ldb, int ldc, const float* __restrict__ bias,
      long long sA, long long sB, long long sC)
{
    __shared__ __align__(16) float As_hi[64*20], As_lo[64*20];
    __shared__ __align__(16) float Bs_hi[128*20], Bs_lo[128*20];

    {
        const int z = blockIdx.z, bt = z / SK, s = z % SK;
        A  += (size_t)bt * sA + (size_t)s * K;
        if (BT) Bm += (size_t)bt * sB + (size_t)s * K;
        else    Bm += (size_t)bt * sB + (size_t)s * K * ldb;
        C  += (size_t)z * sC;
    }

    const int tid  = threadIdx.x;
    const int lane = tid & 31, wid = tid >> 5;
    const int m0 = blockIdx.y * 64, n0 = blockIdx.x * 128;
    const int am = (wid & 1) * 32;
    const int an = (wid >> 1) * 32;

    const unsigned aH = (unsigned)__cvta_generic_to_shared(As_hi);
    const unsigned aL = (unsigned)__cvta_generic_to_shared(As_lo);
    const unsigned bH = (unsigned)__cvta_generic_to_shared(Bs_hi);
    const unsigned bL = (unsigned)__cvta_generic_to_shared(Bs_lo);

    float acc[2][4][4];
#pragma unroll
    for (int i = 0; i < 2; i++)
#pragma unroll
        for (int j = 0; j < 4; j++)
#pragma unroll
            for (int q = 0; q < 4; q++) acc[i][j][q] = 0.f;

    const int arow = tid >> 2, akq = tid & 3;           // A loader map
    const int bnn = tid >> 1, bh8 = (tid & 1) * 8;      // BT-B loader map
    const int nnk = tid >> 4, nnq = tid & 15;           // NN-B loader map

    float4 va, vb0, vb1;
    auto loadG = [&](int k0) {
        va = make_float4(0.f, 0.f, 0.f, 0.f);
        if (m0 + arow < M)
            va = *(const float4*)&A[(size_t)(m0+arow)*lda + k0 + 4*akq];
        vb0 = make_float4(0.f,0.f,0.f,0.f); vb1 = vb0;
        if (BT) {
            if (n0 + bnn < N) {
                const float* src = &Bm[(size_t)(n0+bnn)*ldb + k0 + bh8];
                vb0 = *(const float4*)src;
                vb1 = *(const float4*)(src + 4);
            }
        } else {
            const float* src = &Bm[(size_t)(k0+nnk)*ldb + n0 + 8*nnq];
            vb0 = *(const float4*)src;
            vb1 = *(const float4*)(src + 4);
        }
    };
    auto storeS = [&]() {
        {
            float4 h4, l4;
            tsplit(va.x, h4.x, l4.x); tsplit(va.y, h4.y, l4.y);
            tsplit(va.z, h4.z, l4.z); tsplit(va.w, h4.w, l4.w);
            int w = swz(arow, akq);
            *(float4*)&As_hi[w] = h4;
            *(float4*)&As_lo[w] = l4;
        }
        if (BT) {
            int cb = (tid & 1) * 2;
            float4 h4, l4;
            tsplit(vb0.x, h4.x, l4.x); tsplit(vb0.y, h4.y, l4.y);
            tsplit(vb0.z, h4.z, l4.z); tsplit(vb0.w, h4.w, l4.w);
            int w = swz(bnn, cb);
            *(float4*)&Bs_hi[w] = h4; *(float4*)&Bs_lo[w] = l4;
            tsplit(vb1.x, h4.x, l4.x); tsplit(vb1.y, h4.y, l4.y);
            tsplit(vb1.z, h4.z, l4.z); tsplit(vb1.w, h4.w, l4.w);
            w = swz(bnn, cb + 1);
            *(float4*)&Bs_hi[w] = h4; *(float4*)&Bs_lo[w] = l4;
        } else {
            const float* p0 = (const float*)&vb0;
            const float* p1 = (const float*)&vb1;
#pragma unroll
            for (int e = 0; e < 4; e++) {
                float hv, lv;
                int nl = 8*nnq + e;
                int w = swz(nl, nnk >> 2) + (nnk & 3);
                tsplit(p0[e], hv, lv); Bs_hi[w] = hv; Bs_lo[w] = lv;
                nl += 4; w = swz(nl, nnk >> 2) + (nnk & 3);
                tsplit(p1[e], hv, lv); Bs_hi[w] = hv; Bs_lo[w] = lv;
            }
        }
    };

    const int nch = K >> 4;
    loadG(0);
    for (int ch = 0; ch < nch; ch++) {
        storeS();
        __syncthreads();
        if (ch + 1 < nch) loadG((ch + 1) << 4);   // overlap LDG with compute
#pragma unroll
        for (int half = 0; half < 2; half++) {
            const int kc = half * 8;
            unsigned ah[2][4], al[2][4], bh[4][2], bl[4][2];
#pragma unroll
            for (int i = 0; i < 2; i++) {
                int row = am + 16*i + (lane & 15);
                int chunk = (kc >> 2) + (lane >> 4);
                unsigned off = 4u * (unsigned)swz(row, chunk);
                ldm4(ah[i], aH + off);
                ldm4(al[i], aL + off);
            }
#pragma unroll
            for (int g = 0; g < 2; g++) {
                int row = an + 16*g + (lane & 7) + ((lane >> 4) << 3);
                int chunk = (kc >> 2) + ((lane >> 3) & 1);
                unsigned off = 4u * (unsigned)swz(row, chunk);
                unsigned r[4];
                ldm4(r, bH + off);
                bh[2*g][0] = r[0]; bh[2*g][1] = r[1];
                bh[2*g+1][0] = r[2]; bh[2*g+1][1] = r[3];
                ldm4(r, bL + off);
                bl[2*g][0] = r[0]; bl[2*g][1] = r[1];
                bl[2*g+1][0] = r[2]; bl[2*g+1][1] = r[3];
            }
#pragma unroll
            for (int i = 0; i < 2; i++)
#pragma unroll
                for (int j = 0; j < 4; j++) {
                    mma8(acc[i][j], ah[i], bh[j]);
                    mma8(acc[i][j], ah[i], bl[j]);
                    mma8(acc[i][j], al[i], bh[j]);
                }
        }
        __syncthreads();
    }

#pragma unroll
    for (int i = 0; i < 2; i++) {
#pragma unroll
        for (int j = 0; j < 4; j++) {
            int r0 = m0 + am + 16*i + (lane >> 2);
            int c0 = n0 + an + 8*j + (lane & 3) * 2;
            float b0 = 0.f, b1 = 0.f;
            if (bias) {
                if (c0 < N)     b0 = bias[c0];
                if (c0 + 1 < N) b1 = bias[c0 + 1];
            }
            if (r0 < M) {
                float* p = &C[(size_t)r0*ldc + c0];
                if (c0 < N)     p[0] = acc[i][j][0] + b0;
                if (c0 + 1 < N) p[1] = acc[i][j][1] + b1;
            }
            if (r0 + 8 < M) {
                float* p = &C[(size_t)(r0+8)*ldc + c0];
                if (c0 < N)     p[0] = acc[i][j][2] + b0;
                if (c0 + 1 < N) p[1] = acc[i][j][3] + b1;
            }
        }
    }
}

// ---------------- tgemmps: rec gemm, PRESPLIT B (W_hh hi/lo), prefetched ----
__global__ void __launch_bounds__(256)
tgemmps(const float* __restrict__ A,
        const float* __restrict__ Bhi, const float* __restrict__ Blo,
        float* __restrict__ C, int M, int N, int K,
        int lda, int ldb, int ldc, const float* __restrict__ bias)
{
    __shared__ __align__(16) float As_hi[64*20], As_lo[64*20];
    __shared__ __align__(16) float Bs_hi[128*20], Bs_lo[128*20];

    const int tid  = threadIdx.x;
    const int lane = tid & 31, wid = tid >> 5;
    const int m0 = blockIdx.y * 64, n0 = blockIdx.x * 128;
    const int am = (wid & 1) * 32;
    const int an = (wid >> 1) * 32;

    const unsigned aH = (unsigned)__cvta_generic_to_shared(As_hi);
    const unsigned aL = (unsigned)__cvta_generic_to_shared(As_lo);
    const unsigned bH = (unsigned)__cvta_generic_to_shared(Bs_hi);
    const unsigned bL = (unsigned)__cvta_generic_to_shared(Bs_lo);

    float acc[2][4][4];
#pragma unroll
    for (int i = 0; i < 2; i++)
#pragma unroll
        for (int j = 0; j < 4; j++)
#pragma unroll
            for (int q = 0; q < 4; q++) acc[i][j][q] = 0.f;

    const int arow = tid >> 2, akq = tid & 3;
    const int bnn = tid >> 1, bh8 = (tid & 1) * 8;

    float4 va, vh0, vh1, vl0, vl1;
    auto loadG = [&](int k0) {
        va = *(const float4*)&A[(size_t)(m0+arow)*lda + k0 + 4*akq];
        size_t boff = (size_t)(n0+bnn)*ldb + k0 + bh8;
        vh0 = *(const float4*)&Bhi[boff];
        vh1 = *(const float4*)&Bhi[boff + 4];
        vl0 = *(const float4*)&Blo[boff];
        vl1 = *(const float4*)&Blo[boff + 4];
    };
    auto storeS = [&]() {
        {
            float4 h4, l4;
            tsplit(va.x, h4.x, l4.x); tsplit(va.y, h4.y, l4.y);
            tsplit(va.z, h4.z, l4.z); tsplit(va.w, h4.w, l4.w);
            int w = swz(arow, akq);
            *(float4*)&As_hi[w] = h4;
            *(float4*)&As_lo[w] = l4;
        }
        {
            int cb = (tid & 1) * 2;
            int w = swz(bnn, cb);
            *(float4*)&Bs_hi[w] = vh0; *(float4*)&Bs_lo[w] = vl0;
            w = swz(bnn, cb + 1);
            *(float4*)&Bs_hi[w] = vh1; *(float4*)&Bs_lo[w] = vl1;
        }
    };

    const int nch = K >> 4;
    loadG(0);
    for (int ch = 0; ch < nch; ch++) {
        storeS();
        __syncthreads();
        if (ch + 1 < nch) loadG((ch + 1) << 4);   // overlap LDG with compute
#pragma unroll
        for (int half = 0; half < 2; half++) {
            const int kc = half * 8;
            unsigned ah[2][4], al[2][4], bh[4][2], bl[4][2];
#pragma unroll
            for (int i = 0; i < 2; i++) {
                int row = am + 16*i + (lane & 15);
                int chunk = (kc >> 2) + (lane >> 4);
                unsigned off = 4u * (unsigned)swz(row, chunk);
                ldm4(ah[i], aH + off);
                ldm4(al[i], aL + off);
            }
#pragma unroll
            for (int g = 0; g < 2; g++) {
                int row = an + 16*g + (lane & 7) + ((lane >> 4) << 3);
                int chunk = (kc >> 2) + ((lane >> 3) & 1);
                unsigned off = 4u * (unsigned)swz(row, chunk);
                unsigned r[4];
                ldm4(r, bH + off);
                bh[2*g][0] = r[0]; bh[2*g][1] = r[1];
                bh[2*g+1][0] = r[2]; bh[2*g+1][1] = r[3];
                ldm4(r, bL + off);
                bl[2*g][0] = r[0]; bl[2*g][1] = r[1];
                bl[2*g+1][0] = r[2]; bl[2*g+1][1] = r[3];
            }
#pragma unroll
            for (int i = 0; i < 2; i++)
#pragma unroll
                for (int j = 0; j < 4; j++) {
                    mma8(acc[i][j], ah[i], bh[j]);
                    mma8(acc[i][j], ah[i], bl[j]);
                    mma8(acc[i][j], al[i], bh[j]);
                }
        }
        __syncthreads();
    }

#pragma unroll
    for (int i = 0; i < 2; i++) {
#pragma unroll
        for (int j = 0; j < 4; j++) {
            int r0 = m0 + am + 16*i + (lane >> 2);
            int c0 = n0 + an + 8*j + (lane & 3) * 2;
            float b0 = bias[c0], b1 = bias[c0 + 1];
            float* p = &C[(size_t)r0*ldc + c0];
            p[0] = acc[i][j][0] + b0;
            p[1] = acc[i][j][1] + b1;
            p = &C[(size_t)(r0+8)*ldc + c0];
            p[0] = acc[i][j][2] + b0;
            p[1] = acc[i][j][3] + b1;
        }
    }
}

// ---------------- mega init: state + pads + transposes + Whh presplit -------
__global__ void mega_init(const float* __restrict__ W_ih,
                          const float* __restrict__ b_ih,
                          const float* __restrict__ b_hh,
                          const float* __restrict__ Wp,
                          const float* __restrict__ lin_W,
                          const float* __restrict__ cls_W,
                          const float* __restrict__ W_hh)
{
    const long long gs = (long long)gridDim.x * blockDim.x;
    const long long id = (long long)blockIdx.x * blockDim.x + threadIdx.x;
    for (long long i = id; i < Bc*Hc; i += gs) { d_h[0][i] = 0.f; d_c[i] = 0.f; }
    for (long long i = id; i < Cc*Hc; i += gs) {
        int c = (int)(i >> 9), h = (int)(i & 511);
        d_WpT[i] = Wp[h*Cc + c];
    }
    for (long long i = id; i < G4; i += gs) {
        d_wihdur[i] = W_ih[(size_t)i*DP1 + Dc];
        d_bsum[i]   = b_ih[i] + b_hh[i];
    }
    for (long long i = id; i < (long long)G4*XP; i += gs) {
        int r = (int)(i / XP), c = (int)(i % XP);
        d_Wihp[i] = (c < DP1) ? W_ih[(size_t)r*DP1 + c] : 0.f;
    }
    for (long long i = id; i < (long long)FEATNP*LWP; i += gs) {
        int r = (int)(i / LWP), c = (int)(i % LWP);
        d_linWp[i] = (r < FEATN && c < DP1) ? lin_W[(size_t)r*DP1 + c] : 0.f;
    }
    for (long long i = id; i < (long long)Kc*D2*Cc; i += gs) {
        int k = (int)(i / (D2*Cc)), rem = (int)(i % (D2*Cc));
        int d = rem / Cc, c = rem % Cc;
        d_cWT[(size_t)k*Cc*D2 + (size_t)c*D2 + d] = cls_W[i];
    }
    for (long long i = id; i < (long long)G4*Hc; i += gs) {
        float h, l; tsplit(W_hh[i], h, l);
        d_Whh_hi[i] = h; d_Whh_lo[i] = l;
    }
}

// ---------------- split-K reduce (E) + padded reduce (x0) -------------------
__global__ void reduce_add(const float* __restrict__ part, float* __restrict__ outp,
                           int n, int nparts, long long stride)
{
    int i = blockIdx.x * blockDim.x + threadIdx.x;
    if (i >= n) return;
    float s = 0.f;
    for (int z = 0; z < nparts; z++) s += part[(size_t)z*stride + i];
    outp[i] = s;
}

__global__ void reduce_x0(const float* __restrict__ lin_b)
{
    int i = blockIdx.x * blockDim.x + threadIdx.x;
    if (i >= Bc*XP) return;
    int row = i / XP, col = i % XP;
    float v = 0.f;
    if (col < DP1)
        v = d_xp[(size_t)row*DP1 + col] + d_xp[(size_t)Bc*DP1 + (size_t)row*DP1 + col]
          + lin_b[col];
    d_x0p[i] = v;
}

// ---------------- prep: cls reduce+softmax, feat, curr_action, durs ---------
__global__ void prep_kernel(const float* __restrict__ S, const float* __restrict__ R,
                            const float* __restrict__ dur_W, const float* __restrict__ dur_b,
                            const float* __restrict__ Wdur, const float* __restrict__ bcls,
                            float* __restrict__ out)
{
    __shared__ float red[256];
    __shared__ float sY[Kc][Cc];
    const int b = blockIdx.x, tid = threadIdx.x;
    const int wid = tid >> 5, lane = tid & 31;

    // classifier: reduce 2*CSK partials + bias, softmax over 48 (3 warps)
    if (wid < Kc) {
        const int k = wid;
        float v1 = bcls[k*Cc + lane];
        float v2 = (lane < 16) ? bcls[k*Cc + lane + 32] : -3.4e38f;
#pragma unroll
        for (int j = 0; j < CSK; j++) {
            size_t o1 = (size_t)(k*CSK + j)*(Bc*Cc) + (size_t)b*Cc;
            size_t o2 = (size_t)(Kc*CSK + k*CSK + j)*(Bc*Cc) + (size_t)b*Cc;
            v1 += d_clsp[o1 + lane] + d_clsp[o2 + lane];
            if (lane < 16) v2 += d_clsp[o1 + lane + 32] + d_clsp[o2 + lane + 32];
        }
        float m = fmaxf(v1, v2);
        for (int o = 16; o; o >>= 1) m = fmaxf(m, __shfl_xor_sync(0xffffffffu, m, o));
        float e1 = expf(v1 - m);
        float e2 = (lane < 16) ? expf(v2 - m) : 0.f;
        float s = e1 + e2;
        for (int o = 16; o; o >>= 1) s += __shfl_xor_sync(0xffffffffu, s, o);
        float inv = 1.f / s;
        sY[k][lane] = e1 * inv;
        if (lane < 16) sY[k][lane + 32] = e2 * inv;
    }
    __syncthreads();

    float* fr = d_feat + (size_t)b * FEATNP;
    for (int i = tid; i < Kc*Cc; i += 256) {
        int k = i / Cc, c = i - k*Cc;
        fr[i] = sY[k][c];
    }
    for (int i = tid; i < Kc*Dc; i += 256) {
        int k = i >> 10, d = i & 1023;
        fr[Kc*Cc + i]         = S[((size_t)k*Bc + b)*Dc + d];
        fr[Kc*Cc + Kc*Dc + i] = R[((size_t)k*Bc + b)*Dc + d];
    }
    if (tid < FEATNP - FEATN) fr[FEATN + tid] = 0.f;   // zero pad cols
    for (int i = tid; i < Cc; i += 256)
        out[O2 + (size_t)b*Cc + i] = sY[0][i] + sY[1][i] + sY[2][i];
    float pd = 0.f;
    for (int i = tid; i < Kc*Dc; i += 256) {
        int k = i >> 10, d = i & 1023;
        pd += R[((size_t)k*Bc + b)*Dc + d] * dur_W[i];
    }
    red[tid] = pd; __syncthreads();
    for (int s = 128; s > 0; s >>= 1) { if (tid < s) red[tid] += red[tid + s]; __syncthreads(); }
    if (tid == 0) out[O3 + (size_t)b*(Tc+1)] = red[0] + dur_b[0];
    __syncthreads();
    for (int k = 0; k < Kc; k++) {
        float ps = 0.f;
        for (int d = tid; d < Dc; d += 256)
            ps += S[((size_t)k*Bc + b)*Dc + d] * Wdur[d];
        red[tid] = ps; __syncthreads();
        for (int s = 128; s > 0; s >>= 1) { if (tid < s) red[tid] += red[tid + s]; __syncthreads(); }
        if (tid == 0) d_sdur[b*Kc + k] = red[0];
        __syncthreads();
    }
}

// fused per-step kernel: LSTM elementwise + logits/probs/argmax + attention +
// dur ; one block per b, 512 threads (16 warps). bsum already folded in GEMMs.
__global__ void __launch_bounds__(512)
step_kernel(const float* __restrict__ S, const float* __restrict__ bp,
            const float* __restrict__ Wdur, const float* __restrict__ bdur,
            float* __restrict__ out, int t, int sel)
{
    __shared__ float sh[Hc];
    __shared__ float slog[Cc];
    __shared__ float sscore[3];
    __shared__ float saw[3];
    __shared__ float sred[16];
    const int b  = blockIdx.x;
    const int th = threadIdx.x;
    const int wid = th >> 5, lane = th & 31;
    const float* h_in = d_h[sel];
    float* h_out = d_h[sel ^ 1];

    float g[4];
    if (t == 0) {
#pragma unroll
        for (int j = 0; j < 4; j++) g[j] = d_gx0[(size_t)b*G4 + j*Hc + th];
    } else {
        int lab = d_labels[b];
        float dp = d_dur[b];
#pragma unroll
        for (int j = 0; j < 4; j++) {
            int gi = j*Hc + th;
            g[j] = d_gates[(size_t)b*G4 + gi] + d_E[(size_t)lab*G4 + gi]
                 + dp * d_wihdur[gi];
        }
    }
    float ig = 1.f / (1.f + expf(-g[0]));
    float fg = 1.f / (1.f + expf(-g[1]));
    float gg = tanhf(g[2]);
    float og = 1.f / (1.f + expf(-g[3]));
    int idx = b*Hc + th;
    float cn = fg * d_c[idx] + ig * gg;
    d_c[idx] = cn;
    float hn = og * tanhf(cn);
    h_out[idx] = hn;
    sh[th] = hn;
    float hp = h_in[idx] * Wdur[Dc + th];
    for (int o = 16; o; o >>= 1) hp += __shfl_xor_sync(0xffffffffu, hp, o);
    if (lane == 0) sred[wid] = hp;
    __syncthreads();

    for (int cc = wid; cc < Cc; cc += 16) {
        float s = 0.f;
        const float* wr = d_WpT + (size_t)cc*Hc;
        for (int j = lane; j < Hc; j += 32) s += sh[j] * wr[j];
        for (int o = 16; o; o >>= 1) s += __shfl_xor_sync(0xffffffffu, s, o);
        if (lane == 0) slog[cc] = s + bp[cc];
    }
    if (wid < 3) {
        float s = 0.f;
        const float* Pr = d_P + ((size_t)wid*Bc + b)*Hc;
        for (int j = lane; j < Hc; j += 32) s += sh[j] * Pr[j];
        for (int o = 16; o; o >>= 1) s += __shfl_xor_sync(0xffffffffu, s, o);
        if (lane == 0) sscore[wid] = s * 0.03125f;  // 1/sqrt(1024)
    }
    __syncthreads();

    if (wid == 0) {
        float v1 = slog[lane];
        float v2 = (lane < Cc - 32) ? slog[32 + lane] : -3.4e38f;
        float m = fmaxf(v1, v2);
        for (int o = 16; o; o >>= 1) m = fmaxf(m, __shfl_xor_sync(0xffffffffu, m, o));
        float e1 = expf(v1 - m);
        float e2 = (lane < Cc - 32) ? expf(v2 - m) : 0.f;
        float s = e1 + e2;
        for (int o = 16; o; o >>= 1) s += __shfl_xor_sync(0xffffffffu, s, o);
        float inv = 1.f / s;
        size_t pb = O1 + ((size_t)b*Tc + t)*Cc;
        out[pb + lane] = e1 * inv;
        if (lane < Cc - 32) out[pb + 32 + lane] = e2 * inv;
        float bv; int bi;
        if (lane < Cc - 32 && v2 > v1) { bv = v2; bi = 32 + lane; }
        else                           { bv = v1; bi = lane; }
        for (int o = 16; o; o >>= 1) {
            float ov = __shfl_xor_sync(0xffffffffu, bv, o);
            int   oi = __shfl_xor_sync(0xffffffffu, bi, o);
            if (ov > bv || (ov == bv && oi < bi)) { bv = ov; bi = oi; }
        }
        float hv = (lane < 16) ? sred[lane] : 0.f;
        for (int o = 8; o; o >>= 1) hv += __shfl_xor_sync(0xffffffffu, hv, o);
        if (lane == 0) {
            out[O0 + (size_t)t*Bc + b] = (float)bi;
            d_labels[b] = bi;
            float s0 = sscore[0], s1 = sscore[1], s2 = sscore[2];
            float sm = fmaxf(s0, fmaxf(s1, s2));
            float a0 = expf(s0 - sm), a1 = expf(s1 - sm), a2 = expf(s2 - sm);
            float z = 1.f / (a0 + a1 + a2);
            a0 *= z; a1 *= z; a2 *= z;
            saw[0] = a0; saw[1] = a1; saw[2] = a2;
            float dur = a0*d_sdur[b*Kc] + a1*d_sdur[b*Kc+1] + a2*d_sdur[b*Kc+2]
                      + hv + bdur[0];
            out[O3 + (size_t)b*(Tc+1) + t + 1] = dur;
            d_dur[b] = dur;
        }
    }
    __syncthreads();

    float a0 = saw[0], a1 = saw[1], a2 = saw[2];
    size_t ab = O4 + ((size_t)t*Bc + b)*Dc;
    const float* S0 = S + (size_t)b*Dc;
    const float* S1 = S + ((size_t)Bc + b)*Dc;
    const float* S2 = S + ((size_t)2*Bc + b)*Dc;
    for (int d = th; d < Dc; d += 512)
        out[ab + d] = a0*S0[d] + a1*S1[d] + a2*S2[d];
}

// ---------------- host ------------------------------------------------------
extern "C" void kernel_launch(void* const* d_in, const int* in_sizes, int n_in,
                              void* d_out, int out_size)
{
    const float* S     = (const float*)d_in[0];
    const float* R     = (const float*)d_in[1];
    const float* cls_W = (const float*)d_in[2];
    const float* cls_b = (const float*)d_in[3];
    const float* dur_W = (const float*)d_in[4];
    const float* dur_b = (const float*)d_in[5];
    const float* lin_W = (const float*)d_in[6];
    const float* lin_b = (const float*)d_in[7];
    const float* W_ih  = (const float*)d_in[8];
    const float* W_hh  = (const float*)d_in[9];
    const float* b_ih  = (const float*)d_in[10];
    const float* b_hh  = (const float*)d_in[11];
    const float* Wp    = (const float*)d_in[12];
    const float* bp    = (const float*)d_in[13];
    const float* Wdur  = (const float*)d_in[14];
    const float* bdur  = (const float*)d_in[15];
    const float* embed = (const float*)d_in[16];
    const float* Wattn = (const float*)d_in[17];
    float* out = (float*)d_out;

    float *pfeat, *px0p, *pxp, *pgx0, *pE, *pEp, *pP, *pgates, *ph, *pbsum;
    float *pWihp, *plinWp, *pclsp, *pcWT, *pWhh_hi, *pWhh_lo;
    cudaGetSymbolAddress((void**)&pfeat,   d_feat);
    cudaGetSymbolAddress((void**)&px0p,    d_x0p);
    cudaGetSymbolAddress((void**)&pxp,     d_xp);
    cudaGetSymbolAddress((void**)&pgx0,    d_gx0);
    cudaGetSymbolAddress((void**)&pE,      d_E);
    cudaGetSymbolAddress((void**)&pEp,     d_Ep);
    cudaGetSymbolAddress((void**)&pP,      d_P);
    cudaGetSymbolAddress((void**)&pgates,  d_gates);
    cudaGetSymbolAddress((void**)&ph,      d_h);
    cudaGetSymbolAddress((void**)&pbsum,   d_bsum);
    cudaGetSymbolAddress((void**)&pWihp,   d_Wihp);
    cudaGetSymbolAddress((void**)&plinWp,  d_linWp);
    cudaGetSymbolAddress((void**)&pclsp,   d_clsp);
    cudaGetSymbolAddress((void**)&pcWT,    d_cWT);
    cudaGetSymbolAddress((void**)&pWhh_hi, d_Whh_hi);
    cudaGetSymbolAddress((void**)&pWhh_lo, d_Whh_lo);

    mega_init<<<1024, 256>>>(W_ih, b_ih, b_hh, Wp, lin_W, cls_W, W_hh);

    // P = S_flat @ Wattn^T  [1536 x 512, K=1024]  (96 blocks, early for ncu)
    tgemm<true, 1><<<dim3(4, 24), 256>>>(
        S, Wattn, pP, Kc*Bc, Hc, Dc, Dc, Dc, Hc, nullptr, 0, 0, 0);

    // classifier logits: split-K 4 per (k, S/R part) -> partial buffers
    tgemm<true, CSK><<<dim3(1, 8, Kc*CSK), 256>>>(
        S, pcWT, pclsp, Bc, Cc, Dc/CSK, Dc, D2, Cc, nullptr,
        (long long)Bc*Dc, (long long)Cc*D2, (long long)Bc*Cc);
    tgemm<true, CSK><<<dim3(1, 8, Kc*CSK), 256>>>(
        R, pcWT + Dc, pclsp + (size_t)Kc*CSK*Bc*Cc, Bc, Cc, Dc/CSK, Dc, D2, Cc,
        nullptr, (long long)Bc*Dc, (long long)Cc*D2, (long long)Bc*Cc);

    prep_kernel<<<Bc, 256>>>(S, R, dur_W, dur_b, Wdur, cls_b, out);

    // x0 = feat @ lin_W + lin_b  [512 x 1025, K=6304]  split-K 2 (144 blocks)
    tgemm<false, 2><<<dim3(9, 8, 2), 256>>>(
        pfeat, plinWp, pxp, Bc, DP1, FEATNP/2, FEATNP, LWP, DP1, nullptr,
        0, 0, (long long)Bc*DP1);
    reduce_x0<<<(Bc*XP + 255)/256, 256>>>(lin_b);
    // gx0 = x0 @ W_ih^T + bsum  [512 x 2048, K=1040]  (128 blocks)
    tgemm<true, 1><<<dim3(16, 8), 256>>>(
        px0p, pWihp, pgx0, Bc, G4, XP, XP, XP, G4, pbsum, 0, 0, 0);
    // E = embed @ W_ih[:, :D]^T  [48 x 2048, K=1024]  split-K 4 (64 blocks)
    tgemm<true, 4><<<dim3(16, 1, 4), 256>>>(
        embed, pWihp, pEp, Cc, G4, Dc/4, Dc, XP, G4, nullptr,
        0, 0, (long long)Cc*G4);
    reduce_add<<<(Cc*G4 + 255)/256, 256>>>(pEp, pE, Cc*G4, 4, (long long)Cc*G4);

    int sel = 0;
    for (int t = 0; t < Tc; t++) {
        if (t > 0)
            tgemmps<<<dim3(16, 8), 256>>>(
                ph + (size_t)sel*Bc*Hc, pWhh_hi, pWhh_lo, pgates,
                Bc, G4, Hc, Hc, Hc, G4, pbsum);
        step_kernel<<<Bc, 512>>>(S, bp, Wdur, bdur, out, t, sel);
        sel ^= 1;
    }
}